// round 8
// baseline (speedup 1.0000x reference)
#include <cuda_runtime.h>
#include <math.h>
#include <float.h>

// ---------------- problem constants ----------------
// B=16, Tq=2048, Tk=512, DIM_IN=80, DIM_HIDDEN=512, ATTN_CH=80
// K path: keys[16,512,512] -conv3,relu-> h[1024, 16*512] -1x1-> kf[80, 16*512]
// Q path: queries[16,80,2048] -conv3,relu-> q1[160, 16*2048] -1x1,relu-> q2[80,...] -1x1-> qf[80,...]
// Attention: d = sqrt(max(q2+k2-2qk,1e-12)); mask -> -FLT_MAX; softmax over Tk.
// Output: attn [16,1,2048,512] then attn_logp (same shape), fp32.

#define NK 8192      // 16*512
#define NQ 32768     // 16*2048

__device__ float g_h [1024u * NK];   // 33.5 MB
__device__ float g_kf[80u * NK];
__device__ float g_q1[160u * NQ];
__device__ float g_q2[80u * NQ];
__device__ float g_qf[80u * NQ];

// ---------------------------------------------------------------------------
// conv3 GEMM: C[M,N] = relu( A[M, Cin*3] @ B + bias ), B[k3, n] = X[b, ci, t+dt-1]
// n = b*Tlen + t, k3 = ci*3+dt. BM=BN=128, BK=8, 256 threads, 8x8 microtile.
// ---------------------------------------------------------------------------
template<bool RELU>
__global__ __launch_bounds__(256)
void conv3_gemm(const float* __restrict__ A, const float* __restrict__ X,
                const float* __restrict__ bias, float* __restrict__ C,
                int M, int Cin, int Tlen, int N, int tshift)
{
    const int K3 = Cin * 3;
    __shared__ float As[8][128];
    __shared__ float Bs[8][132];

    const int tid = threadIdx.x;
    const int tx = tid & 15, ty = tid >> 4;
    const int n0 = blockIdx.x * 128;
    const int m0 = blockIdx.y * 128;
    const int tmask = Tlen - 1;

    const int arow = tid >> 1, aquad = (tid & 1) * 4;
    const int brow = tid >> 5, bcol = (tid & 31) * 4;

    float acc[8][8];
#pragma unroll
    for (int i = 0; i < 8; i++)
#pragma unroll
        for (int j = 0; j < 8; j++) acc[i][j] = 0.f;

    for (int k0 = 0; k0 < K3; k0 += 8) {
        // stage global -> regs
        float4 av = make_float4(0.f, 0.f, 0.f, 0.f);
        if (m0 + arow < M)
            av = *(const float4*)(A + (size_t)(m0 + arow) * K3 + k0 + aquad);
        float bv[4];
        {
            int k3 = k0 + brow;
            int ci = k3 / 3;
            int dt = k3 - ci * 3;
#pragma unroll
            for (int e = 0; e < 4; e++) {
                int n = n0 + bcol + e;
                int b = n >> tshift;
                int t = (n & tmask) + dt - 1;
                bv[e] = ((unsigned)t < (unsigned)Tlen)
                        ? X[((size_t)b * Cin + ci) * Tlen + t] : 0.f;
            }
        }
        __syncthreads();
        As[aquad + 0][arow] = av.x;
        As[aquad + 1][arow] = av.y;
        As[aquad + 2][arow] = av.z;
        As[aquad + 3][arow] = av.w;
#pragma unroll
        for (int e = 0; e < 4; e++) Bs[brow][bcol + e] = bv[e];
        __syncthreads();

#pragma unroll
        for (int kk = 0; kk < 8; kk++) {
            float a[8], bb[8];
            *(float4*)(a)      = *(const float4*)&As[kk][ty * 4];
            *(float4*)(a + 4)  = *(const float4*)&As[kk][64 + ty * 4];
            *(float4*)(bb)     = *(const float4*)&Bs[kk][tx * 4];
            *(float4*)(bb + 4) = *(const float4*)&Bs[kk][64 + tx * 4];
#pragma unroll
            for (int i = 0; i < 8; i++)
#pragma unroll
                for (int j = 0; j < 8; j++) acc[i][j] += a[i] * bb[j];
        }
    }

#pragma unroll
    for (int i = 0; i < 8; i++) {
        int m = m0 + ((i < 4) ? (ty * 4 + i) : (64 + ty * 4 + i - 4));
        if (m < M) {
            float bia = bias[m];
#pragma unroll
            for (int j = 0; j < 8; j++) {
                int n = n0 + ((j < 4) ? (tx * 4 + j) : (64 + tx * 4 + j - 4));
                float v = acc[i][j] + bia;
                if (RELU) v = fmaxf(v, 0.f);
                C[(size_t)m * N + n] = v;
            }
        }
    }
}

// ---------------------------------------------------------------------------
// 1x1 GEMM: C[M,N] = act( A[M,K] @ B[K,N] + bias ). Same tiling.
// ---------------------------------------------------------------------------
template<bool RELU>
__global__ __launch_bounds__(256)
void gemm1x1(const float* __restrict__ A, const float* __restrict__ Bsrc,
             const float* __restrict__ bias, float* __restrict__ C,
             int M, int K, int N)
{
    __shared__ float As[8][128];
    __shared__ float Bs[8][132];

    const int tid = threadIdx.x;
    const int tx = tid & 15, ty = tid >> 4;
    const int n0 = blockIdx.x * 128;
    const int m0 = blockIdx.y * 128;

    const int arow = tid >> 1, aquad = (tid & 1) * 4;
    const int brow = tid >> 5, bcol = (tid & 31) * 4;

    float acc[8][8];
#pragma unroll
    for (int i = 0; i < 8; i++)
#pragma unroll
        for (int j = 0; j < 8; j++) acc[i][j] = 0.f;

    for (int k0 = 0; k0 < K; k0 += 8) {
        float4 av = make_float4(0.f, 0.f, 0.f, 0.f);
        if (m0 + arow < M)
            av = *(const float4*)(A + (size_t)(m0 + arow) * K + k0 + aquad);
        float4 bvv = *(const float4*)(Bsrc + (size_t)(k0 + brow) * N + n0 + bcol);
        __syncthreads();
        As[aquad + 0][arow] = av.x;
        As[aquad + 1][arow] = av.y;
        As[aquad + 2][arow] = av.z;
        As[aquad + 3][arow] = av.w;
        *(float4*)&Bs[brow][bcol] = bvv;
        __syncthreads();

#pragma unroll
        for (int kk = 0; kk < 8; kk++) {
            float a[8], bb[8];
            *(float4*)(a)      = *(const float4*)&As[kk][ty * 4];
            *(float4*)(a + 4)  = *(const float4*)&As[kk][64 + ty * 4];
            *(float4*)(bb)     = *(const float4*)&Bs[kk][tx * 4];
            *(float4*)(bb + 4) = *(const float4*)&Bs[kk][64 + tx * 4];
#pragma unroll
            for (int i = 0; i < 8; i++)
#pragma unroll
                for (int j = 0; j < 8; j++) acc[i][j] += a[i] * bb[j];
        }
    }

#pragma unroll
    for (int i = 0; i < 8; i++) {
        int m = m0 + ((i < 4) ? (ty * 4 + i) : (64 + ty * 4 + i - 4));
        if (m < M) {
            float bia = bias[m];
#pragma unroll
            for (int j = 0; j < 8; j++) {
                int n = n0 + ((j < 4) ? (tx * 4 + j) : (64 + tx * 4 + j - 4));
                float v = acc[i][j] + bia;
                if (RELU) v = fmaxf(v, 0.f);
                C[(size_t)m * N + n] = v;
            }
        }
    }
}

// ---------------------------------------------------------------------------
// Attention: per block = (64 q rows of one batch) x full 512 k.
// Computes qk GEMM (K=80) into smem as d = sqrt(max(q2+k2-2qk,1e-12)), applies
// mask, writes logp, then row softmax from smem, writes attn.
// Mask is read as 32-bit words: the harness widens jnp.bool_ to a 4-byte
// dtype (int32 1 or float32 1.0f); word != 0 is true for both.
// ---------------------------------------------------------------------------
#define DST 520
#define ATTN_SMEM ((80*64 + 80*128 + 64 + 128 + 64*DST) * 4)

__global__ __launch_bounds__(256)
void attn_kernel(const float* __restrict__ qf, const float* __restrict__ kf,
                 const int* __restrict__ mask,
                 float* __restrict__ attn_out, float* __restrict__ logp_out)
{
    extern __shared__ float sm[];
    float* Qs  = sm;                  // [80][64]
    float* Ks  = Qs + 80 * 64;        // [80][128]
    float* q2s = Ks + 80 * 128;       // [64]
    float* k2s = q2s + 64;            // [128]
    float* Dsm = k2s + 128;           // [64][DST]

    const int b  = blockIdx.y;
    const int q0 = blockIdx.x * 64;
    const int tid = threadIdx.x;
    const int tx = tid & 15, ty = tid >> 4;

    for (int idx = tid; idx < 80 * 64; idx += 256) {
        int c = idx >> 6, qi = idx & 63;
        Qs[c * 64 + qi] = qf[(size_t)c * NQ + b * 2048 + q0 + qi];
    }
    __syncthreads();
    if (tid < 64) {
        float s = 0.f;
        for (int c = 0; c < 80; c++) { float v = Qs[c * 64 + tid]; s += v * v; }
        q2s[tid] = s;
    }

    for (int kc = 0; kc < 512; kc += 128) {
        __syncthreads();  // protect Ks/k2s from previous chunk readers
        for (int idx = tid; idx < 80 * 128; idx += 256) {
            int c = idx >> 7, ki = idx & 127;
            Ks[c * 128 + ki] = kf[(size_t)c * NK + b * 512 + kc + ki];
        }
        __syncthreads();
        if (tid < 128) {
            float s = 0.f;
            for (int c = 0; c < 80; c++) { float v = Ks[c * 128 + tid]; s += v * v; }
            k2s[tid] = s;
        }
        float acc[4][8];
#pragma unroll
        for (int i = 0; i < 4; i++)
#pragma unroll
            for (int j = 0; j < 8; j++) acc[i][j] = 0.f;

        for (int c = 0; c < 80; c++) {
            float a[4], bb[8];
            *(float4*)(a)      = *(const float4*)&Qs[c * 64 + ty * 4];
            *(float4*)(bb)     = *(const float4*)&Ks[c * 128 + tx * 4];
            *(float4*)(bb + 4) = *(const float4*)&Ks[c * 128 + 64 + tx * 4];
#pragma unroll
            for (int i = 0; i < 4; i++)
#pragma unroll
                for (int j = 0; j < 8; j++) acc[i][j] += a[i] * bb[j];
        }
        __syncthreads();  // k2s ready for everyone

#pragma unroll
        for (int i = 0; i < 4; i++) {
            int qi = ty * 4 + i;
#pragma unroll
            for (int j = 0; j < 8; j++) {
                int kil = (j < 4) ? (tx * 4 + j) : (64 + tx * 4 + j - 4);
                int kg = kc + kil;
                float d2 = q2s[qi] + k2s[kil] - 2.f * acc[i][j];
                float d = sqrtf(fmaxf(d2, 1e-12f));
                if (mask[b * 512 + kg] == 0) d = -FLT_MAX;
                Dsm[qi * DST + kg] = d;
            }
        }
    }
    __syncthreads();

    // write logp (coalesced float4)
    const size_t rowbase = ((size_t)b * 2048 + q0) * 512;
    for (int idx = tid; idx < 64 * 128; idx += 256) {
        int qi = idx >> 7;
        int c4 = (idx & 127) * 4;
        float4 v = *(const float4*)&Dsm[qi * DST + c4];
        *(float4*)&logp_out[rowbase + (size_t)qi * 512 + c4] = v;
    }

    // row softmax: warp w handles rows w*8 .. w*8+7
    const int warp = tid >> 5, lane = tid & 31;
    for (int r = 0; r < 8; r++) {
        int qi = warp * 8 + r;
        float vals[16];
        float mx = -FLT_MAX;
#pragma unroll
        for (int j = 0; j < 16; j++) {
            vals[j] = Dsm[qi * DST + lane + j * 32];
            mx = fmaxf(mx, vals[j]);
        }
#pragma unroll
        for (int off = 16; off; off >>= 1)
            mx = fmaxf(mx, __shfl_xor_sync(0xffffffffu, mx, off));
        float s = 0.f;
#pragma unroll
        for (int j = 0; j < 16; j++) { vals[j] = __expf(vals[j] - mx); s += vals[j]; }
#pragma unroll
        for (int off = 16; off; off >>= 1)
            s += __shfl_xor_sync(0xffffffffu, s, off);
        float inv = 1.f / s;
#pragma unroll
        for (int j = 0; j < 16; j++)
            attn_out[rowbase + (size_t)qi * 512 + lane + j * 32] = vals[j] * inv;
    }
}

// ---------------------------------------------------------------------------
extern "C" void kernel_launch(void* const* d_in, const int* in_sizes, int n_in,
                              void* d_out, int out_size)
{
    const float* queries = (const float*)d_in[0];
    const float* keys    = (const float*)d_in[1];
    const int*   mask    = (const int*)d_in[2];
    const float* kw1 = (const float*)d_in[3];
    const float* kb1 = (const float*)d_in[4];
    const float* kw2 = (const float*)d_in[5];
    const float* kb2 = (const float*)d_in[6];
    const float* qw1 = (const float*)d_in[7];
    const float* qb1 = (const float*)d_in[8];
    const float* qw2 = (const float*)d_in[9];
    const float* qb2 = (const float*)d_in[10];
    const float* qw3 = (const float*)d_in[11];
    const float* qb3 = (const float*)d_in[12];

    float *h, *kf, *q1, *q2, *qf;
    cudaGetSymbolAddress((void**)&h,  g_h);
    cudaGetSymbolAddress((void**)&kf, g_kf);
    cudaGetSymbolAddress((void**)&q1, g_q1);
    cudaGetSymbolAddress((void**)&q2, g_q2);
    cudaGetSymbolAddress((void**)&qf, g_qf);

    // K path
    conv3_gemm<true ><<<dim3(NK / 128, 8), 256>>>(kw1, keys, kb1, h, 1024, 512, 512, NK, 9);
    gemm1x1  <false><<<dim3(NK / 128, 1), 256>>>(kw2, h, kb2, kf, 80, 1024, NK);
    // Q path
    conv3_gemm<true ><<<dim3(NQ / 128, 2), 256>>>(qw1, queries, qb1, q1, 160, 80, 2048, NQ, 11);
    gemm1x1  <true ><<<dim3(NQ / 128, 1), 256>>>(qw2, q1, qb2, q2, 80, 160, NQ);
    gemm1x1  <false><<<dim3(NQ / 128, 1), 256>>>(qw3, q2, qb3, qf, 80, 80, NQ);

    // Attention + softmax
    float* attn = (float*)d_out;
    float* logp = attn + (size_t)16 * 2048 * 512;
    cudaFuncSetAttribute(attn_kernel, cudaFuncAttributeMaxDynamicSharedMemorySize, ATTN_SMEM);
    attn_kernel<<<dim3(2048 / 64, 16), 256, ATTN_SMEM>>>(qf, kf, mask, attn, logp);
}

// round 9
// speedup vs baseline: 1.0465x; 1.0465x over previous
#include <cuda_runtime.h>
#include <math.h>
#include <float.h>

// ---------------- problem constants ----------------
// B=16, Tq=2048, Tk=512, DIM_IN=80, DIM_HIDDEN=512, ATTN_CH=80
// K path: keys[16,512,512] -conv3,relu-> h[1024, 16*512] -1x1-> kf[80, 16*512]
// Q path: queries[16,80,2048] -conv3,relu-> q1[160, 16*2048] -1x1,relu-> q2[80,...] -1x1-> qf[80,...]
// Attention: d = sqrt(max(q2+k2-2qk,1e-12)); mask -> -FLT_MAX; softmax over Tk.
// Output: attn [16,1,2048,512] then attn_logp (same shape), fp32.

#define NK 8192      // 16*512
#define NQ 32768     // 16*2048

__device__ float g_h [1024u * NK];   // 33.5 MB
__device__ float g_kf[80u * NK];
__device__ float g_q1[160u * NQ];
__device__ float g_q2[80u * NQ];
__device__ float g_qf[80u * NQ];

// ---------------------------------------------------------------------------
// conv3 GEMM: C[M,N] = relu( A[M, Cin*3] @ B + bias ), B[k3, n] = X[b, ci, t+dt-1]
// n = b*Tlen + t, k3 = ci*3+dt. BM=BN=128, BK=8, 256 threads, 8x8 microtile.
// ---------------------------------------------------------------------------
template<bool RELU>
__global__ __launch_bounds__(256)
void conv3_gemm(const float* __restrict__ A, const float* __restrict__ X,
                const float* __restrict__ bias, float* __restrict__ C,
                int M, int Cin, int Tlen, int N, int tshift)
{
    const int K3 = Cin * 3;
    __shared__ float As[8][128];
    __shared__ float Bs[8][132];

    const int tid = threadIdx.x;
    const int tx = tid & 15, ty = tid >> 4;
    const int n0 = blockIdx.x * 128;
    const int m0 = blockIdx.y * 128;
    const int tmask = Tlen - 1;

    const int arow = tid >> 1, aquad = (tid & 1) * 4;
    const int brow = tid >> 5, bcol = (tid & 31) * 4;

    float acc[8][8];
#pragma unroll
    for (int i = 0; i < 8; i++)
#pragma unroll
        for (int j = 0; j < 8; j++) acc[i][j] = 0.f;

    for (int k0 = 0; k0 < K3; k0 += 8) {
        // stage global -> regs
        float4 av = make_float4(0.f, 0.f, 0.f, 0.f);
        if (m0 + arow < M)
            av = *(const float4*)(A + (size_t)(m0 + arow) * K3 + k0 + aquad);
        float bv[4];
        {
            int k3 = k0 + brow;
            int ci = k3 / 3;
            int dt = k3 - ci * 3;
#pragma unroll
            for (int e = 0; e < 4; e++) {
                int n = n0 + bcol + e;
                int b = n >> tshift;
                int t = (n & tmask) + dt - 1;
                bv[e] = ((unsigned)t < (unsigned)Tlen)
                        ? X[((size_t)b * Cin + ci) * Tlen + t] : 0.f;
            }
        }
        __syncthreads();
        As[aquad + 0][arow] = av.x;
        As[aquad + 1][arow] = av.y;
        As[aquad + 2][arow] = av.z;
        As[aquad + 3][arow] = av.w;
#pragma unroll
        for (int e = 0; e < 4; e++) Bs[brow][bcol + e] = bv[e];
        __syncthreads();

#pragma unroll
        for (int kk = 0; kk < 8; kk++) {
            float a[8], bb[8];
            *(float4*)(a)      = *(const float4*)&As[kk][ty * 4];
            *(float4*)(a + 4)  = *(const float4*)&As[kk][64 + ty * 4];
            *(float4*)(bb)     = *(const float4*)&Bs[kk][tx * 4];
            *(float4*)(bb + 4) = *(const float4*)&Bs[kk][64 + tx * 4];
#pragma unroll
            for (int i = 0; i < 8; i++)
#pragma unroll
                for (int j = 0; j < 8; j++) acc[i][j] += a[i] * bb[j];
        }
    }

#pragma unroll
    for (int i = 0; i < 8; i++) {
        int m = m0 + ((i < 4) ? (ty * 4 + i) : (64 + ty * 4 + i - 4));
        if (m < M) {
            float bia = bias[m];
#pragma unroll
            for (int j = 0; j < 8; j++) {
                int n = n0 + ((j < 4) ? (tx * 4 + j) : (64 + tx * 4 + j - 4));
                float v = acc[i][j] + bia;
                if (RELU) v = fmaxf(v, 0.f);
                C[(size_t)m * N + n] = v;
            }
        }
    }
}

// ---------------------------------------------------------------------------
// 1x1 GEMM: C[M,N] = act( A[M,K] @ B[K,N] + bias ). Same tiling.
// ---------------------------------------------------------------------------
template<bool RELU>
__global__ __launch_bounds__(256)
void gemm1x1(const float* __restrict__ A, const float* __restrict__ Bsrc,
             const float* __restrict__ bias, float* __restrict__ C,
             int M, int K, int N)
{
    __shared__ float As[8][128];
    __shared__ float Bs[8][132];

    const int tid = threadIdx.x;
    const int tx = tid & 15, ty = tid >> 4;
    const int n0 = blockIdx.x * 128;
    const int m0 = blockIdx.y * 128;

    const int arow = tid >> 1, aquad = (tid & 1) * 4;
    const int brow = tid >> 5, bcol = (tid & 31) * 4;

    float acc[8][8];
#pragma unroll
    for (int i = 0; i < 8; i++)
#pragma unroll
        for (int j = 0; j < 8; j++) acc[i][j] = 0.f;

    for (int k0 = 0; k0 < K; k0 += 8) {
        float4 av = make_float4(0.f, 0.f, 0.f, 0.f);
        if (m0 + arow < M)
            av = *(const float4*)(A + (size_t)(m0 + arow) * K + k0 + aquad);
        float4 bvv = *(const float4*)(Bsrc + (size_t)(k0 + brow) * N + n0 + bcol);
        __syncthreads();
        As[aquad + 0][arow] = av.x;
        As[aquad + 1][arow] = av.y;
        As[aquad + 2][arow] = av.z;
        As[aquad + 3][arow] = av.w;
        *(float4*)&Bs[brow][bcol] = bvv;
        __syncthreads();

#pragma unroll
        for (int kk = 0; kk < 8; kk++) {
            float a[8], bb[8];
            *(float4*)(a)      = *(const float4*)&As[kk][ty * 4];
            *(float4*)(a + 4)  = *(const float4*)&As[kk][64 + ty * 4];
            *(float4*)(bb)     = *(const float4*)&Bs[kk][tx * 4];
            *(float4*)(bb + 4) = *(const float4*)&Bs[kk][64 + tx * 4];
#pragma unroll
            for (int i = 0; i < 8; i++)
#pragma unroll
                for (int j = 0; j < 8; j++) acc[i][j] += a[i] * bb[j];
        }
    }

#pragma unroll
    for (int i = 0; i < 8; i++) {
        int m = m0 + ((i < 4) ? (ty * 4 + i) : (64 + ty * 4 + i - 4));
        if (m < M) {
            float bia = bias[m];
#pragma unroll
            for (int j = 0; j < 8; j++) {
                int n = n0 + ((j < 4) ? (tx * 4 + j) : (64 + tx * 4 + j - 4));
                float v = acc[i][j] + bia;
                if (RELU) v = fmaxf(v, 0.f);
                C[(size_t)m * N + n] = v;
            }
        }
    }
}

// ---------------------------------------------------------------------------
// Attention: per block = (64 q rows of one batch) x full 512 k.
// Computes qk GEMM (K=80) into smem as d = sqrt(max(q2+k2-2qk,1e-12)), applies
// mask, writes logp, then row softmax from smem, writes attn.
// Mask is read as 32-bit words: the harness widens jnp.bool_ to a 4-byte
// dtype (int32 1 or float32 1.0f); word != 0 is true for both.
// ---------------------------------------------------------------------------
#define DST 520
#define ATTN_SMEM ((80*64 + 80*128 + 64 + 128 + 64*DST) * 4)

__global__ __launch_bounds__(256)
void attn_kernel(const float* __restrict__ qf, const float* __restrict__ kf,
                 const int* __restrict__ mask,
                 float* __restrict__ attn_out, float* __restrict__ logp_out)
{
    extern __shared__ float sm[];
    float* Qs  = sm;                  // [80][64]
    float* Ks  = Qs + 80 * 64;        // [80][128]
    float* q2s = Ks + 80 * 128;       // [64]
    float* k2s = q2s + 64;            // [128]
    float* Dsm = k2s + 128;           // [64][DST]

    const int b  = blockIdx.y;
    const int q0 = blockIdx.x * 64;
    const int tid = threadIdx.x;
    const int tx = tid & 15, ty = tid >> 4;

    for (int idx = tid; idx < 80 * 64; idx += 256) {
        int c = idx >> 6, qi = idx & 63;
        Qs[c * 64 + qi] = qf[(size_t)c * NQ + b * 2048 + q0 + qi];
    }
    __syncthreads();
    if (tid < 64) {
        float s = 0.f;
        for (int c = 0; c < 80; c++) { float v = Qs[c * 64 + tid]; s += v * v; }
        q2s[tid] = s;
    }

    for (int kc = 0; kc < 512; kc += 128) {
        __syncthreads();  // protect Ks/k2s from previous chunk readers
        for (int idx = tid; idx < 80 * 128; idx += 256) {
            int c = idx >> 7, ki = idx & 127;
            Ks[c * 128 + ki] = kf[(size_t)c * NK + b * 512 + kc + ki];
        }
        __syncthreads();
        if (tid < 128) {
            float s = 0.f;
            for (int c = 0; c < 80; c++) { float v = Ks[c * 128 + tid]; s += v * v; }
            k2s[tid] = s;
        }
        float acc[4][8];
#pragma unroll
        for (int i = 0; i < 4; i++)
#pragma unroll
            for (int j = 0; j < 8; j++) acc[i][j] = 0.f;

        for (int c = 0; c < 80; c++) {
            float a[4], bb[8];
            *(float4*)(a)      = *(const float4*)&Qs[c * 64 + ty * 4];
            *(float4*)(bb)     = *(const float4*)&Ks[c * 128 + tx * 4];
            *(float4*)(bb + 4) = *(const float4*)&Ks[c * 128 + 64 + tx * 4];
#pragma unroll
            for (int i = 0; i < 4; i++)
#pragma unroll
                for (int j = 0; j < 8; j++) acc[i][j] += a[i] * bb[j];
        }
        __syncthreads();  // k2s ready for everyone

#pragma unroll
        for (int i = 0; i < 4; i++) {
            int qi = ty * 4 + i;
#pragma unroll
            for (int j = 0; j < 8; j++) {
                int kil = (j < 4) ? (tx * 4 + j) : (64 + tx * 4 + j - 4);
                int kg = kc + kil;
                float d2 = q2s[qi] + k2s[kil] - 2.f * acc[i][j];
                float d = sqrtf(fmaxf(d2, 1e-12f));
                if (mask[b * 512 + kg] == 0) d = -FLT_MAX;
                Dsm[qi * DST + kg] = d;
            }
        }
    }
    __syncthreads();

    // write logp (coalesced float4)
    const size_t rowbase = ((size_t)b * 2048 + q0) * 512;
    for (int idx = tid; idx < 64 * 128; idx += 256) {
        int qi = idx >> 7;
        int c4 = (idx & 127) * 4;
        float4 v = *(const float4*)&Dsm[qi * DST + c4];
        *(float4*)&logp_out[rowbase + (size_t)qi * 512 + c4] = v;
    }

    // row softmax: warp w handles rows w*8 .. w*8+7
    const int warp = tid >> 5, lane = tid & 31;
    for (int r = 0; r < 8; r++) {
        int qi = warp * 8 + r;
        float vals[16];
        float mx = -FLT_MAX;
#pragma unroll
        for (int j = 0; j < 16; j++) {
            vals[j] = Dsm[qi * DST + lane + j * 32];
            mx = fmaxf(mx, vals[j]);
        }
#pragma unroll
        for (int off = 16; off; off >>= 1)
            mx = fmaxf(mx, __shfl_xor_sync(0xffffffffu, mx, off));
        float s = 0.f;
#pragma unroll
        for (int j = 0; j < 16; j++) { vals[j] = __expf(vals[j] - mx); s += vals[j]; }
#pragma unroll
        for (int off = 16; off; off >>= 1)
            s += __shfl_xor_sync(0xffffffffu, s, off);
        float inv = 1.f / s;
#pragma unroll
        for (int j = 0; j < 16; j++)
            attn_out[rowbase + (size_t)qi * 512 + lane + j * 32] = vals[j] * inv;
    }
}

// ---------------------------------------------------------------------------
extern "C" void kernel_launch(void* const* d_in, const int* in_sizes, int n_in,
                              void* d_out, int out_size)
{
    const float* queries = (const float*)d_in[0];
    const float* keys    = (const float*)d_in[1];
    const int*   mask    = (const int*)d_in[2];
    const float* kw1 = (const float*)d_in[3];
    const float* kb1 = (const float*)d_in[4];
    const float* kw2 = (const float*)d_in[5];
    const float* kb2 = (const float*)d_in[6];
    const float* qw1 = (const float*)d_in[7];
    const float* qb1 = (const float*)d_in[8];
    const float* qw2 = (const float*)d_in[9];
    const float* qb2 = (const float*)d_in[10];
    const float* qw3 = (const float*)d_in[11];
    const float* qb3 = (const float*)d_in[12];

    float *h, *kf, *q1, *q2, *qf;
    cudaGetSymbolAddress((void**)&h,  g_h);
    cudaGetSymbolAddress((void**)&kf, g_kf);
    cudaGetSymbolAddress((void**)&q1, g_q1);
    cudaGetSymbolAddress((void**)&q2, g_q2);
    cudaGetSymbolAddress((void**)&qf, g_qf);

    // K path
    conv3_gemm<true ><<<dim3(NK / 128, 8), 256>>>(kw1, keys, kb1, h, 1024, 512, 512, NK, 9);
    gemm1x1  <false><<<dim3(NK / 128, 1), 256>>>(kw2, h, kb2, kf, 80, 1024, NK);
    // Q path
    conv3_gemm<true ><<<dim3(NQ / 128, 2), 256>>>(qw1, queries, qb1, q1, 160, 80, 2048, NQ, 11);
    gemm1x1  <true ><<<dim3(NQ / 128, 1), 256>>>(qw2, q1, qb2, q2, 80, 160, NQ);
    gemm1x1  <false><<<dim3(NQ / 128, 1), 256>>>(qw3, q2, qb3, qf, 80, 80, NQ);

    // Attention + softmax
    float* attn = (float*)d_out;
    float* logp = attn + (size_t)16 * 2048 * 512;
    cudaFuncSetAttribute(attn_kernel, cudaFuncAttributeMaxDynamicSharedMemorySize, ATTN_SMEM);
    attn_kernel<<<dim3(2048 / 64, 16), 256, ATTN_SMEM>>>(qf, kf, mask, attn, logp);
}

// round 11
// speedup vs baseline: 1.9764x; 1.8886x over previous
#include <cuda_runtime.h>
#include <cuda_bf16.h>
#include <math.h>
#include <float.h>
#include <stdint.h>

#define NK 8192      // 16*512
#define NQ 32768     // 16*2048

// K-path bf16 hi/lo buffers
__device__ __nv_bfloat16 g_Bthi[8192u * 1536];
__device__ __nv_bfloat16 g_Btlo[8192u * 1536];
__device__ __nv_bfloat16 g_w1hi[1024u * 1536];
__device__ __nv_bfloat16 g_w1lo[1024u * 1536];
__device__ __nv_bfloat16 g_hThi[8192u * 1024];
__device__ __nv_bfloat16 g_hTlo[8192u * 1024];
__device__ __nv_bfloat16 g_w2hi[128u * 1024];
__device__ __nv_bfloat16 g_w2lo[128u * 1024];
__device__ float g_kf[80u * NK];
// Q-path fp32 buffers
__device__ float g_q1[160u * NQ];
__device__ float g_q2[80u * NQ];
__device__ float g_qf[80u * NQ];

// =========================== PTX helpers (sm_80+ baseline only) ===========================
__device__ __forceinline__ uint32_t smem_u32(const void* p) {
    return (uint32_t)__cvta_generic_to_shared(p);
}
#define SW128(x) ((x) ^ (((x) >> 3) & 0x70))

__device__ __forceinline__ void cpa16(uint32_t dst, const void* src) {
    asm volatile("cp.async.cg.shared.global [%0], [%1], 16;\n" :: "r"(dst), "l"(src));
}
#define CP_COMMIT() asm volatile("cp.async.commit_group;\n" ::: "memory")

__device__ __forceinline__ void ldsm4(uint32_t* r, uint32_t addr) {
    asm volatile("ldmatrix.sync.aligned.m8n8.x4.shared.b16 {%0,%1,%2,%3}, [%4];"
                 : "=r"(r[0]), "=r"(r[1]), "=r"(r[2]), "=r"(r[3]) : "r"(addr));
}

__device__ __forceinline__ void mma_bf16(float* c, const uint32_t* a, const uint32_t* b) {
    asm volatile(
        "mma.sync.aligned.m16n8k16.row.col.f32.bf16.bf16.f32 "
        "{%0,%1,%2,%3}, {%4,%5,%6,%7}, {%8,%9}, {%0,%1,%2,%3};\n"
        : "+f"(c[0]), "+f"(c[1]), "+f"(c[2]), "+f"(c[3])
        : "r"(a[0]), "r"(a[1]), "r"(a[2]), "r"(a[3]), "r"(b[0]), "r"(b[1]));
}

// =========================== prep kernels ===========================
__global__ void split_pad(const float* __restrict__ in, __nv_bfloat16* __restrict__ hi,
                          __nv_bfloat16* __restrict__ lo, int realRows, int cols, int total)
{
    int idx = blockIdx.x * 256 + threadIdx.x;
    if (idx >= total) return;
    int row = idx / cols;
    float v = (row < realRows) ? in[idx] : 0.f;
    __nv_bfloat16 h = __float2bfloat16(v);
    hi[idx] = h;
    lo[idx] = __float2bfloat16(v - __bfloat162float(h));
}

// Bt[n][ci*3+dt] = keys[b][ci][t+dt-1], n=b*512+t, zero-padded ends; hi/lo split.
__global__ __launch_bounds__(256)
void build_Bt(const float* __restrict__ keys,
              __nv_bfloat16* __restrict__ bhi, __nv_bfloat16* __restrict__ blo)
{
    __shared__ float sk[64][131];
    const int tid = threadIdx.x;
    const int nt = blockIdx.x;          // 64 n-tiles of 128
    const int cc = blockIdx.y * 64;     // ci chunk
    const int b  = nt >> 2;
    const int t0 = (nt & 3) * 128;
    const int n0 = b * 512 + t0;

    for (int idx = tid; idx < 64 * 130; idx += 256) {
        int cl = idx / 130, tt = idx - cl * 130;
        int ts = t0 + tt - 1;
        sk[cl][tt] = ((unsigned)ts < 512u)
                     ? keys[((size_t)b * 512 + cc + cl) * 512 + ts] : 0.f;
    }
    __syncthreads();
    for (int idx = tid; idx < 128 * 192; idx += 256) {
        int tl = idx / 192, r = idx - tl * 192;
        int cl = r / 3, dt = r - cl * 3;
        float v = sk[cl][tl + dt];
        __nv_bfloat16 h = __float2bfloat16(v);
        size_t o = (size_t)(n0 + tl) * 1536 + cc * 3 + r;
        bhi[o] = h;
        blo[o] = __float2bfloat16(v - __bfloat162float(h));
    }
}

// ===================== mma.sync bf16x3 GEMM (K path) =====================
// C[i][j] = sum_k A[i][k]*B[j][k], computed as hi*hi + lo*hi + hi*lo.
// CTA tile 128(i) x 128(j), K-chunk 64, 2-stage cp.async pipeline, SW128 smem.
// 8 warps (2x4): warp tile 64(i) x 32(j). mma m16n8k16: M<-i, N<-j.
// MODE 1: hT[i=n][j=m] = relu(C + kb1[j]) -> bf16 hi/lo pairs (stride 1024)
// MODE 2: kf[i=m<80][j=n] = C + kb2[i]    -> fp32 (stride NK)
#define MMK_SMEM 131072

template<int MODE>
__global__ __launch_bounds__(256)
void mmk(const __nv_bfloat16* __restrict__ aHi, const __nv_bfloat16* __restrict__ aLo,
         const __nv_bfloat16* __restrict__ bHi, const __nv_bfloat16* __restrict__ bLo,
         const float* __restrict__ bias,
         __nv_bfloat16* __restrict__ outHi, __nv_bfloat16* __restrict__ outLo,
         float* __restrict__ outF, int Kdim)
{
    extern __shared__ __align__(1024) char smx[];
    const int tid  = threadIdx.x;
    const int wid  = tid >> 5, lane = tid & 31;
    const int nCh  = Kdim >> 6;

    const int aRow0 = (MODE == 1) ? blockIdx.x * 128 : 0;
    const int bRow0 = (MODE == 1) ? blockIdx.y * 128 : blockIdx.x * 128;

    const int warp_i = (wid >> 2) * 64;   // 0 or 64
    const int warp_j = (wid & 3) * 32;    // 0,32,64,96

    const uint32_t sbase = smem_u32(smx);
    const uint32_t stA[2] = { sbase, sbase + 65536u };  // per stage: Ahi|Alo|Bhi|Blo 16KB each

    auto load_chunk = [&](int c, int s) {
        const uint32_t base = stA[s];
        const size_t cb = (size_t)c * 64;
#pragma unroll
        for (int it = 0; it < 16; it++) {
            int idx = tid + it * 256;                 // 0..4095
            int mat = idx >> 10;                      // 0 Ahi, 1 Alo, 2 Bhi, 3 Blo
            int r   = (idx & 1023) >> 3;
            int g   = idx & 7;
            const __nv_bfloat16* srcm =
                (mat == 0) ? aHi : (mat == 1) ? aLo : (mat == 2) ? bHi : bLo;
            int row0 = (mat < 2) ? aRow0 : bRow0;
            cpa16(base + mat * 16384u + SW128((r << 7) + (g << 4)),
                  srcm + (size_t)(row0 + r) * Kdim + cb + g * 8);
        }
    };

    load_chunk(0, 0); CP_COMMIT();
    load_chunk(1, 1); CP_COMMIT();

    float acc[4][4][4];
#pragma unroll
    for (int a = 0; a < 4; a++)
#pragma unroll
        for (int b = 0; b < 4; b++)
#pragma unroll
            for (int r = 0; r < 4; r++) acc[a][b][r] = 0.f;

    for (int c = 0; c < nCh; c++) {
        const int s = c & 1;
        if (c + 1 < nCh) asm volatile("cp.async.wait_group 1;" ::: "memory");
        else             asm volatile("cp.async.wait_group 0;" ::: "memory");
        __syncthreads();

        const uint32_t A_hi = stA[s], A_lo = stA[s] + 16384u;
        const uint32_t B_hi = stA[s] + 32768u, B_lo = stA[s] + 49152u;

#pragma unroll
        for (int ks = 0; ks < 4; ks++) {
            const int kb = ks * 32;
            uint32_t ah[4][4], al[4][4], bh[4][2], bl[4][2];
            {
                const int g = lane >> 3;
                const int arow = (lane & 7) + ((g & 1) << 3);
                const int akc  = kb + ((g >> 1) << 4);
#pragma unroll
                for (int tn = 0; tn < 4; tn++) {
                    uint32_t off = SW128(((warp_i + tn * 16 + arow) << 7) + akc);
                    ldsm4(ah[tn], A_hi + off);
                    ldsm4(al[tn], A_lo + off);
                }
                const int brow = (lane & 7) + ((g >> 1) << 3);   // tile within pair
                const int bkc  = kb + ((g & 1) << 4);
#pragma unroll
                for (int p = 0; p < 2; p++) {
                    uint32_t off = SW128(((warp_j + p * 16 + brow) << 7) + bkc);
                    uint32_t r4[4];
                    ldsm4(r4, B_hi + off);
                    bh[p * 2][0] = r4[0]; bh[p * 2][1] = r4[1];
                    bh[p * 2 + 1][0] = r4[2]; bh[p * 2 + 1][1] = r4[3];
                    ldsm4(r4, B_lo + off);
                    bl[p * 2][0] = r4[0]; bl[p * 2][1] = r4[1];
                    bl[p * 2 + 1][0] = r4[2]; bl[p * 2 + 1][1] = r4[3];
                }
            }
#pragma unroll
            for (int tn = 0; tn < 4; tn++)
#pragma unroll
                for (int tm = 0; tm < 4; tm++) {
                    mma_bf16(acc[tn][tm], ah[tn], bh[tm]);
                    mma_bf16(acc[tn][tm], al[tn], bh[tm]);
                    mma_bf16(acc[tn][tm], ah[tn], bl[tm]);
                }
        }
        __syncthreads();
        if (c + 2 < nCh) { load_chunk(c + 2, s); CP_COMMIT(); }
    }

    // ---- epilogue ----
    const int li = lane >> 2;          // 0..7
    const int lj = (lane & 3) * 2;     // 0,2,4,6
#pragma unroll
    for (int tn = 0; tn < 4; tn++) {
#pragma unroll
        for (int tm = 0; tm < 4; tm++) {
            int i0 = warp_i + tn * 16 + li;
            int j0 = warp_j + tm * 8 + lj;
            if (MODE == 1) {
                float bj0 = bias[bRow0 + j0], bj1 = bias[bRow0 + j0 + 1];
#pragma unroll
                for (int h = 0; h < 2; h++) {      // h=0: row i0, h=1: row i0+8
                    float v0 = fmaxf(acc[tn][tm][h * 2 + 0] + bj0, 0.f);
                    float v1 = fmaxf(acc[tn][tm][h * 2 + 1] + bj1, 0.f);
                    __nv_bfloat16 h0 = __float2bfloat16(v0);
                    __nv_bfloat16 h1 = __float2bfloat16(v1);
                    __nv_bfloat162 hv; hv.x = h0; hv.y = h1;
                    __nv_bfloat162 lv;
                    lv.x = __float2bfloat16(v0 - __bfloat162float(h0));
                    lv.y = __float2bfloat16(v1 - __bfloat162float(h1));
                    size_t o = (size_t)(aRow0 + i0 + h * 8) * 1024 + bRow0 + j0;
                    *(__nv_bfloat162*)&outHi[o] = hv;
                    *(__nv_bfloat162*)&outLo[o] = lv;
                }
            } else {
#pragma unroll
                for (int h = 0; h < 2; h++) {
                    int i = i0 + h * 8;
                    if (i < 80) {
                        float bi = bias[i];
                        float2 v = make_float2(acc[tn][tm][h * 2 + 0] + bi,
                                               acc[tn][tm][h * 2 + 1] + bi);
                        *(float2*)&outF[(size_t)i * NK + bRow0 + j0] = v;
                    }
                }
            }
        }
    }
}

// ===================== fp32 Q-path kernels (unchanged) =====================
template<bool RELU>
__global__ __launch_bounds__(256)
void conv3_gemm(const float* __restrict__ A, const float* __restrict__ X,
                const float* __restrict__ bias, float* __restrict__ C,
                int M, int Cin, int Tlen, int N, int tshift)
{
    const int K3 = Cin * 3;
    __shared__ float As[8][128];
    __shared__ float Bs[8][132];
    const int tid = threadIdx.x;
    const int tx = tid & 15, ty = tid >> 4;
    const int n0 = blockIdx.x * 128;
    const int m0 = blockIdx.y * 128;
    const int tmask = Tlen - 1;
    const int arow = tid >> 1, aquad = (tid & 1) * 4;
    const int brow = tid >> 5, bcol = (tid & 31) * 4;
    float acc[8][8];
#pragma unroll
    for (int i = 0; i < 8; i++)
#pragma unroll
        for (int j = 0; j < 8; j++) acc[i][j] = 0.f;
    for (int k0 = 0; k0 < K3; k0 += 8) {
        float4 av = make_float4(0.f, 0.f, 0.f, 0.f);
        if (m0 + arow < M)
            av = *(const float4*)(A + (size_t)(m0 + arow) * K3 + k0 + aquad);
        float bv[4];
        {
            int k3 = k0 + brow;
            int ci = k3 / 3, dt = k3 - ci * 3;
#pragma unroll
            for (int e = 0; e < 4; e++) {
                int n = n0 + bcol + e;
                int b = n >> tshift;
                int t = (n & tmask) + dt - 1;
                bv[e] = ((unsigned)t < (unsigned)Tlen)
                        ? X[((size_t)b * Cin + ci) * Tlen + t] : 0.f;
            }
        }
        __syncthreads();
        As[aquad + 0][arow] = av.x; As[aquad + 1][arow] = av.y;
        As[aquad + 2][arow] = av.z; As[aquad + 3][arow] = av.w;
#pragma unroll
        for (int e = 0; e < 4; e++) Bs[brow][bcol + e] = bv[e];
        __syncthreads();
#pragma unroll
        for (int kk = 0; kk < 8; kk++) {
            float a[8], bb[8];
            *(float4*)(a)      = *(const float4*)&As[kk][ty * 4];
            *(float4*)(a + 4)  = *(const float4*)&As[kk][64 + ty * 4];
            *(float4*)(bb)     = *(const float4*)&Bs[kk][tx * 4];
            *(float4*)(bb + 4) = *(const float4*)&Bs[kk][64 + tx * 4];
#pragma unroll
            for (int i = 0; i < 8; i++)
#pragma unroll
                for (int j = 0; j < 8; j++) acc[i][j] += a[i] * bb[j];
        }
    }
#pragma unroll
    for (int i = 0; i < 8; i++) {
        int m = m0 + ((i < 4) ? (ty * 4 + i) : (64 + ty * 4 + i - 4));
        if (m < M) {
            float bia = bias[m];
#pragma unroll
            for (int j = 0; j < 8; j++) {
                int n = n0 + ((j < 4) ? (tx * 4 + j) : (64 + tx * 4 + j - 4));
                float v = acc[i][j] + bia;
                if (RELU) v = fmaxf(v, 0.f);
                C[(size_t)m * N + n] = v;
            }
        }
    }
}

template<bool RELU>
__global__ __launch_bounds__(256)
void gemm1x1(const float* __restrict__ A, const float* __restrict__ Bsrc,
             const float* __restrict__ bias, float* __restrict__ C,
             int M, int K, int N)
{
    __shared__ float As[8][128];
    __shared__ float Bs[8][132];
    const int tid = threadIdx.x;
    const int tx = tid & 15, ty = tid >> 4;
    const int n0 = blockIdx.x * 128;
    const int m0 = blockIdx.y * 128;
    const int arow = tid >> 1, aquad = (tid & 1) * 4;
    const int brow = tid >> 5, bcol = (tid & 31) * 4;
    float acc[8][8];
#pragma unroll
    for (int i = 0; i < 8; i++)
#pragma unroll
        for (int j = 0; j < 8; j++) acc[i][j] = 0.f;
    for (int k0 = 0; k0 < K; k0 += 8) {
        float4 av = make_float4(0.f, 0.f, 0.f, 0.f);
        if (m0 + arow < M)
            av = *(const float4*)(A + (size_t)(m0 + arow) * K + k0 + aquad);
        float4 bvv = *(const float4*)(Bsrc + (size_t)(k0 + brow) * N + n0 + bcol);
        __syncthreads();
        As[aquad + 0][arow] = av.x; As[aquad + 1][arow] = av.y;
        As[aquad + 2][arow] = av.z; As[aquad + 3][arow] = av.w;
        *(float4*)&Bs[brow][bcol] = bvv;
        __syncthreads();
#pragma unroll
        for (int kk = 0; kk < 8; kk++) {
            float a[8], bb[8];
            *(float4*)(a)      = *(const float4*)&As[kk][ty * 4];
            *(float4*)(a + 4)  = *(const float4*)&As[kk][64 + ty * 4];
            *(float4*)(bb)     = *(const float4*)&Bs[kk][tx * 4];
            *(float4*)(bb + 4) = *(const float4*)&Bs[kk][64 + tx * 4];
#pragma unroll
            for (int i = 0; i < 8; i++)
#pragma unroll
                for (int j = 0; j < 8; j++) acc[i][j] += a[i] * bb[j];
        }
    }
#pragma unroll
    for (int i = 0; i < 8; i++) {
        int m = m0 + ((i < 4) ? (ty * 4 + i) : (64 + ty * 4 + i - 4));
        if (m < M) {
            float bia = bias[m];
#pragma unroll
            for (int j = 0; j < 8; j++) {
                int n = n0 + ((j < 4) ? (tx * 4 + j) : (64 + tx * 4 + j - 4));
                float v = acc[i][j] + bia;
                if (RELU) v = fmaxf(v, 0.f);
                C[(size_t)m * N + n] = v;
            }
        }
    }
}

// ===================== attention + softmax (unchanged) =====================
#define DST 520
#define ATTN_SMEM ((80*64 + 80*128 + 64 + 128 + 64*DST) * 4)

__global__ __launch_bounds__(256)
void attn_kernel(const float* __restrict__ qf, const float* __restrict__ kf,
                 const int* __restrict__ mask,
                 float* __restrict__ attn_out, float* __restrict__ logp_out)
{
    extern __shared__ float smf[];
    float* Qs  = smf;
    float* Ks  = Qs + 80 * 64;
    float* q2s = Ks + 80 * 128;
    float* k2s = q2s + 64;
    float* Dsm = k2s + 128;

    const int b  = blockIdx.y;
    const int q0 = blockIdx.x * 64;
    const int tid = threadIdx.x;
    const int tx = tid & 15, ty = tid >> 4;

    for (int idx = tid; idx < 80 * 64; idx += 256) {
        int c = idx >> 6, qi = idx & 63;
        Qs[c * 64 + qi] = qf[(size_t)c * NQ + b * 2048 + q0 + qi];
    }
    __syncthreads();
    if (tid < 64) {
        float s = 0.f;
        for (int c = 0; c < 80; c++) { float v = Qs[c * 64 + tid]; s += v * v; }
        q2s[tid] = s;
    }

    for (int kc = 0; kc < 512; kc += 128) {
        __syncthreads();
        for (int idx = tid; idx < 80 * 128; idx += 256) {
            int c = idx >> 7, ki = idx & 127;
            Ks[c * 128 + ki] = kf[(size_t)c * NK + b * 512 + kc + ki];
        }
        __syncthreads();
        if (tid < 128) {
            float s = 0.f;
            for (int c = 0; c < 80; c++) { float v = Ks[c * 128 + tid]; s += v * v; }
            k2s[tid] = s;
        }
        float acc[4][8];
#pragma unroll
        for (int i = 0; i < 4; i++)
#pragma unroll
            for (int j = 0; j < 8; j++) acc[i][j] = 0.f;
        for (int c = 0; c < 80; c++) {
            float a[4], bb[8];
            *(float4*)(a)      = *(const float4*)&Qs[c * 64 + ty * 4];
            *(float4*)(bb)     = *(const float4*)&Ks[c * 128 + tx * 4];
            *(float4*)(bb + 4) = *(const float4*)&Ks[c * 128 + 64 + tx * 4];
#pragma unroll
            for (int i = 0; i < 4; i++)
#pragma unroll
                for (int j = 0; j < 8; j++) acc[i][j] += a[i] * bb[j];
        }
        __syncthreads();
#pragma unroll
        for (int i = 0; i < 4; i++) {
            int qi = ty * 4 + i;
#pragma unroll
            for (int j = 0; j < 8; j++) {
                int kil = (j < 4) ? (tx * 4 + j) : (64 + tx * 4 + j - 4);
                int kg = kc + kil;
                float d2 = q2s[qi] + k2s[kil] - 2.f * acc[i][j];
                float d = sqrtf(fmaxf(d2, 1e-12f));
                if (mask[b * 512 + kg] == 0) d = -FLT_MAX;
                Dsm[qi * DST + kg] = d;
            }
        }
    }
    __syncthreads();

    const size_t rowbase = ((size_t)b * 2048 + q0) * 512;
    for (int idx = tid; idx < 64 * 128; idx += 256) {
        int qi = idx >> 7;
        int c4 = (idx & 127) * 4;
        float4 v = *(const float4*)&Dsm[qi * DST + c4];
        *(float4*)&logp_out[rowbase + (size_t)qi * 512 + c4] = v;
    }

    const int warp = tid >> 5, lane = tid & 31;
    for (int r = 0; r < 8; r++) {
        int qi = warp * 8 + r;
        float vals[16];
        float mx = -FLT_MAX;
#pragma unroll
        for (int j = 0; j < 16; j++) {
            vals[j] = Dsm[qi * DST + lane + j * 32];
            mx = fmaxf(mx, vals[j]);
        }
#pragma unroll
        for (int off = 16; off; off >>= 1)
            mx = fmaxf(mx, __shfl_xor_sync(0xffffffffu, mx, off));
        float s = 0.f;
#pragma unroll
        for (int j = 0; j < 16; j++) { vals[j] = __expf(vals[j] - mx); s += vals[j]; }
#pragma unroll
        for (int off = 16; off; off >>= 1)
            s += __shfl_xor_sync(0xffffffffu, s, off);
        float inv = 1.f / s;
#pragma unroll
        for (int j = 0; j < 16; j++)
            attn_out[rowbase + (size_t)qi * 512 + lane + j * 32] = vals[j] * inv;
    }
}

// ---------------------------------------------------------------------------
extern "C" void kernel_launch(void* const* d_in, const int* in_sizes, int n_in,
                              void* d_out, int out_size)
{
    const float* queries = (const float*)d_in[0];
    const float* keys    = (const float*)d_in[1];
    const int*   mask    = (const int*)d_in[2];
    const float* kw1 = (const float*)d_in[3];
    const float* kb1 = (const float*)d_in[4];
    const float* kw2 = (const float*)d_in[5];
    const float* kb2 = (const float*)d_in[6];
    const float* qw1 = (const float*)d_in[7];
    const float* qb1 = (const float*)d_in[8];
    const float* qw2 = (const float*)d_in[9];
    const float* qb2 = (const float*)d_in[10];
    const float* qw3 = (const float*)d_in[11];
    const float* qb3 = (const float*)d_in[12];

    __nv_bfloat16 *bthi, *btlo, *w1hi, *w1lo, *hthi, *htlo, *w2hi, *w2lo;
    float *kf, *q1, *q2, *qf;
    cudaGetSymbolAddress((void**)&bthi, g_Bthi);
    cudaGetSymbolAddress((void**)&btlo, g_Btlo);
    cudaGetSymbolAddress((void**)&w1hi, g_w1hi);
    cudaGetSymbolAddress((void**)&w1lo, g_w1lo);
    cudaGetSymbolAddress((void**)&hthi, g_hThi);
    cudaGetSymbolAddress((void**)&htlo, g_hTlo);
    cudaGetSymbolAddress((void**)&w2hi, g_w2hi);
    cudaGetSymbolAddress((void**)&w2lo, g_w2lo);
    cudaGetSymbolAddress((void**)&kf, g_kf);
    cudaGetSymbolAddress((void**)&q1, g_q1);
    cudaGetSymbolAddress((void**)&q2, g_q2);
    cudaGetSymbolAddress((void**)&qf, g_qf);

    // ---- K path (tensor cores via mma.sync) ----
    split_pad<<<(1024 * 1536) / 256, 256>>>(kw1, w1hi, w1lo, 1024, 1536, 1024 * 1536);
    split_pad<<<(128 * 1024) / 256, 256>>>(kw2, w2hi, w2lo, 80, 1024, 128 * 1024);
    build_Bt<<<dim3(64, 8), 256>>>(keys, bthi, btlo);
    cudaFuncSetAttribute(mmk<1>, cudaFuncAttributeMaxDynamicSharedMemorySize, MMK_SMEM);
    cudaFuncSetAttribute(mmk<2>, cudaFuncAttributeMaxDynamicSharedMemorySize, MMK_SMEM);
    // GEMM1: hT[8192][1024] = relu(Bt @ W1^T + kb1)
    mmk<1><<<dim3(64, 8), 256, MMK_SMEM>>>(bthi, btlo, w1hi, w1lo, kb1,
                                           hthi, htlo, nullptr, 1536);
    // GEMM2: kf[80][8192] = W2 @ hT^T + kb2
    mmk<2><<<dim3(64, 1), 256, MMK_SMEM>>>(w2hi, w2lo, hthi, htlo, kb2,
                                           nullptr, nullptr, kf, 1024);

    // ---- Q path (fp32) ----
    conv3_gemm<true ><<<dim3(NQ / 128, 2), 256>>>(qw1, queries, qb1, q1, 160, 80, 2048, NQ, 11);
    gemm1x1  <true ><<<dim3(NQ / 128, 1), 256>>>(qw2, q1, qb2, q2, 80, 160, NQ);
    gemm1x1  <false><<<dim3(NQ / 128, 1), 256>>>(qw3, q2, qb3, qf, 80, 80, NQ);

    // ---- attention + softmax ----
    float* attn = (float*)d_out;
    float* logp = attn + (size_t)16 * 2048 * 512;
    cudaFuncSetAttribute(attn_kernel, cudaFuncAttributeMaxDynamicSharedMemorySize, ATTN_SMEM);
    attn_kernel<<<dim3(2048 / 64, 16), 256, ATTN_SMEM>>>(qf, kf, mask, attn, logp);
}

// round 12
// speedup vs baseline: 2.1430x; 1.0843x over previous
#include <cuda_runtime.h>
#include <cuda_bf16.h>
#include <math.h>
#include <float.h>
#include <stdint.h>

#define NK 8192      // 16*512
#define NQ 32768     // 16*2048

// ---- K path buffers ----
__device__ __nv_bfloat16 g_Bthi[8192u * 1536];
__device__ __nv_bfloat16 g_Btlo[8192u * 1536];
__device__ __nv_bfloat16 g_w1hi[1024u * 1536];
__device__ __nv_bfloat16 g_w1lo[1024u * 1536];
__device__ __nv_bfloat16 g_hThi[8192u * 1024];
__device__ __nv_bfloat16 g_hTlo[8192u * 1024];
__device__ __nv_bfloat16 g_w2hi[128u * 1024];
__device__ __nv_bfloat16 g_w2lo[128u * 1024];
__device__ float g_kf[80u * NK];
// ---- Q path buffers (bf16 hi/lo) ----
__device__ __nv_bfloat16 g_BtQhi[32768u * 256];
__device__ __nv_bfloat16 g_BtQlo[32768u * 256];
__device__ __nv_bfloat16 g_qw1hi[256u * 256];
__device__ __nv_bfloat16 g_qw1lo[256u * 256];
__device__ __nv_bfloat16 g_q1hi[32768u * 256];
__device__ __nv_bfloat16 g_q1lo[32768u * 256];
__device__ __nv_bfloat16 g_qw2hi[128u * 256];
__device__ __nv_bfloat16 g_qw2lo[128u * 256];
__device__ __nv_bfloat16 g_q2hi[32768u * 128];
__device__ __nv_bfloat16 g_q2lo[32768u * 128];
__device__ __nv_bfloat16 g_qw3hi[128u * 128];
__device__ __nv_bfloat16 g_qw3lo[128u * 128];
__device__ float g_qf[80u * NQ];
// ---- padded biases ----
__device__ float g_qb1p[256];
__device__ float g_qb2p[128];
__device__ float g_qb3p[128];
__device__ float g_kb2p[128];

// =========================== PTX helpers (sm_80+ baseline) ===========================
__device__ __forceinline__ uint32_t smem_u32(const void* p) {
    return (uint32_t)__cvta_generic_to_shared(p);
}
#define SW128(x) ((x) ^ (((x) >> 3) & 0x70))

__device__ __forceinline__ void cpa16(uint32_t dst, const void* src) {
    asm volatile("cp.async.cg.shared.global [%0], [%1], 16;\n" :: "r"(dst), "l"(src));
}
#define CP_COMMIT() asm volatile("cp.async.commit_group;\n" ::: "memory")

__device__ __forceinline__ void ldsm4(uint32_t* r, uint32_t addr) {
    asm volatile("ldmatrix.sync.aligned.m8n8.x4.shared.b16 {%0,%1,%2,%3}, [%4];"
                 : "=r"(r[0]), "=r"(r[1]), "=r"(r[2]), "=r"(r[3]) : "r"(addr));
}

__device__ __forceinline__ void mma_bf16(float* c, const uint32_t* a, const uint32_t* b) {
    asm volatile(
        "mma.sync.aligned.m16n8k16.row.col.f32.bf16.bf16.f32 "
        "{%0,%1,%2,%3}, {%4,%5,%6,%7}, {%8,%9}, {%0,%1,%2,%3};\n"
        : "+f"(c[0]), "+f"(c[1]), "+f"(c[2]), "+f"(c[3])
        : "r"(a[0]), "r"(a[1]), "r"(a[2]), "r"(a[3]), "r"(b[0]), "r"(b[1]));
}

// =========================== prep kernels ===========================
// Split fp32 [R][C] into bf16 hi/lo [outR][outC], zero-padding rows/cols.
__global__ void split_pad2(const float* __restrict__ in, __nv_bfloat16* __restrict__ hi,
                           __nv_bfloat16* __restrict__ lo, int R, int C, int outC, int total)
{
    int idx = blockIdx.x * 256 + threadIdx.x;
    if (idx >= total) return;
    int row = idx / outC, col = idx - row * outC;
    float v = (row < R && col < C) ? in[row * C + col] : 0.f;
    __nv_bfloat16 h = __float2bfloat16(v);
    hi[idx] = h;
    lo[idx] = __float2bfloat16(v - __bfloat162float(h));
}

__global__ void pad_bias(const float* __restrict__ in, float* __restrict__ out, int C, int outC)
{
    int i = threadIdx.x;
    if (i < outC) out[i] = (i < C) ? in[i] : 0.f;
}

// Bt[n][ci*3+dt] = keys[b][ci][t+dt-1], n=b*512+t; hi/lo split. (K path, Cin=512)
__global__ __launch_bounds__(256)
void build_Bt(const float* __restrict__ keys,
              __nv_bfloat16* __restrict__ bhi, __nv_bfloat16* __restrict__ blo)
{
    __shared__ float sk[64][131];
    const int tid = threadIdx.x;
    const int nt = blockIdx.x;
    const int cc = blockIdx.y * 64;
    const int b  = nt >> 2;
    const int t0 = (nt & 3) * 128;
    const int n0 = b * 512 + t0;

    for (int idx = tid; idx < 64 * 130; idx += 256) {
        int cl = idx / 130, tt = idx - cl * 130;
        int ts = t0 + tt - 1;
        sk[cl][tt] = ((unsigned)ts < 512u)
                     ? keys[((size_t)b * 512 + cc + cl) * 512 + ts] : 0.f;
    }
    __syncthreads();
    for (int idx = tid; idx < 128 * 192; idx += 256) {
        int tl = idx / 192, r = idx - tl * 192;
        int cl = r / 3, dt = r - cl * 3;
        float v = sk[cl][tl + dt];
        __nv_bfloat16 h = __float2bfloat16(v);
        size_t o = (size_t)(n0 + tl) * 1536 + cc * 3 + r;
        bhi[o] = h;
        blo[o] = __float2bfloat16(v - __bfloat162float(h));
    }
}

// BtQ[n][r] = queries[b][r/3][t+r%3-1] for r<240, 0 for 240<=r<256; n=b*2048+t.
__global__ __launch_bounds__(256)
void build_BtQ(const float* __restrict__ queries,
               __nv_bfloat16* __restrict__ bhi, __nv_bfloat16* __restrict__ blo)
{
    __shared__ float sk[80][131];
    const int tid = threadIdx.x;
    const int nt = blockIdx.x;          // 0..255
    const int b  = nt >> 4;
    const int t0 = (nt & 15) * 128;
    const int n0 = b * 2048 + t0;

    for (int idx = tid; idx < 80 * 130; idx += 256) {
        int cl = idx / 130, tt = idx - cl * 130;
        int ts = t0 + tt - 1;
        sk[cl][tt] = ((unsigned)ts < 2048u)
                     ? queries[((size_t)b * 80 + cl) * 2048 + ts] : 0.f;
    }
    __syncthreads();
    for (int idx = tid; idx < 128 * 256; idx += 256) {
        int tl = idx >> 8, r = idx & 255;
        float v = 0.f;
        if (r < 240) {
            int cl = r / 3, dt = r - cl * 3;
            v = sk[cl][tl + dt];
        }
        __nv_bfloat16 h = __float2bfloat16(v);
        size_t o = (size_t)(n0 + tl) * 256 + r;
        bhi[o] = h;
        blo[o] = __float2bfloat16(v - __bfloat162float(h));
    }
}

// ===================== mma.sync bf16x3 GEMM =====================
// C[i][j] = sum_k A[i][k]*B[j][k], hi*hi + lo*hi + hi*lo.
// CTA tile 128x128, K-chunk 64, 2-stage cp.async, SW128 smem, 512 threads.
// 16 warps (4x4): warp tile 32(i) x 32(j).
// MODE 1: out pair[i][j] = relu(C + bias[j]) -> bf16 hi/lo, stride ost.
//         grid: (i-tiles, j-tiles)
// MODE 2: outF[i][j] = C + bias[i] (i < Mreal) -> fp32, stride ost.
//         grid: (j-tiles, 1); A rows = 128 fixed.
#define MMK_SMEM 131072

template<int MODE>
__global__ __launch_bounds__(512)
void mmk(const __nv_bfloat16* __restrict__ aHi, const __nv_bfloat16* __restrict__ aLo,
         const __nv_bfloat16* __restrict__ bHi, const __nv_bfloat16* __restrict__ bLo,
         const float* __restrict__ bias,
         __nv_bfloat16* __restrict__ outHi, __nv_bfloat16* __restrict__ outLo,
         float* __restrict__ outF, int Kdim, int ost, int Mreal)
{
    extern __shared__ __align__(1024) char smx[];
    const int tid  = threadIdx.x;
    const int wid  = tid >> 5, lane = tid & 31;
    const int nCh  = Kdim >> 6;

    const int aRow0 = (MODE == 1) ? blockIdx.x * 128 : 0;
    const int bRow0 = (MODE == 1) ? blockIdx.y * 128 : blockIdx.x * 128;

    const int warp_i = (wid >> 2) * 32;
    const int warp_j = (wid & 3) * 32;

    const uint32_t sbase = smem_u32(smx);
    const uint32_t stA[2] = { sbase, sbase + 65536u };  // per stage: Ahi|Alo|Bhi|Blo 16KB each

    auto load_chunk = [&](int c, int s) {
        const uint32_t base = stA[s];
        const size_t cb = (size_t)c * 64;
#pragma unroll
        for (int it = 0; it < 8; it++) {
            int idx = tid + it * 512;                 // 0..4095
            int mat = idx >> 10;                      // 0 Ahi, 1 Alo, 2 Bhi, 3 Blo
            int r   = (idx & 1023) >> 3;
            int g   = idx & 7;
            const __nv_bfloat16* srcm =
                (mat == 0) ? aHi : (mat == 1) ? aLo : (mat == 2) ? bHi : bLo;
            int row0 = (mat < 2) ? aRow0 : bRow0;
            cpa16(base + mat * 16384u + SW128((r << 7) + (g << 4)),
                  srcm + (size_t)(row0 + r) * Kdim + cb + g * 8);
        }
    };

    load_chunk(0, 0); CP_COMMIT();
    load_chunk(1, 1); CP_COMMIT();

    float acc[2][4][4];
#pragma unroll
    for (int a = 0; a < 2; a++)
#pragma unroll
        for (int b = 0; b < 4; b++)
#pragma unroll
            for (int r = 0; r < 4; r++) acc[a][b][r] = 0.f;

    for (int c = 0; c < nCh; c++) {
        const int s = c & 1;
        if (c + 1 < nCh) asm volatile("cp.async.wait_group 1;" ::: "memory");
        else             asm volatile("cp.async.wait_group 0;" ::: "memory");
        __syncthreads();

        const uint32_t A_hi = stA[s], A_lo = stA[s] + 16384u;
        const uint32_t B_hi = stA[s] + 32768u, B_lo = stA[s] + 49152u;

#pragma unroll
        for (int ks = 0; ks < 4; ks++) {
            const int kb = ks * 32;                   // byte offset: 16 bf16 per step
            uint32_t ah[2][4], al[2][4], bh[4][2], bl[4][2];
            {
                const int g = lane >> 3;
                const int arow = (lane & 7) + ((g & 1) << 3);
                const int akc  = kb + ((g >> 1) << 4);
#pragma unroll
                for (int tn = 0; tn < 2; tn++) {
                    uint32_t off = SW128(((warp_i + tn * 16 + arow) << 7) + akc);
                    ldsm4(ah[tn], A_hi + off);
                    ldsm4(al[tn], A_lo + off);
                }
                const int brow = (lane & 7) + ((g >> 1) << 3);
                const int bkc  = kb + ((g & 1) << 4);
#pragma unroll
                for (int p = 0; p < 2; p++) {
                    uint32_t off = SW128(((warp_j + p * 16 + brow) << 7) + bkc);
                    uint32_t r4[4];
                    ldsm4(r4, B_hi + off);
                    bh[p * 2][0] = r4[0]; bh[p * 2][1] = r4[1];
                    bh[p * 2 + 1][0] = r4[2]; bh[p * 2 + 1][1] = r4[3];
                    ldsm4(r4, B_lo + off);
                    bl[p * 2][0] = r4[0]; bl[p * 2][1] = r4[1];
                    bl[p * 2 + 1][0] = r4[2]; bl[p * 2 + 1][1] = r4[3];
                }
            }
#pragma unroll
            for (int tn = 0; tn < 2; tn++)
#pragma unroll
                for (int tm = 0; tm < 4; tm++) {
                    mma_bf16(acc[tn][tm], ah[tn], bh[tm]);
                    mma_bf16(acc[tn][tm], al[tn], bh[tm]);
                    mma_bf16(acc[tn][tm], ah[tn], bl[tm]);
                }
        }
        __syncthreads();
        if (c + 2 < nCh) { load_chunk(c + 2, s); CP_COMMIT(); }
    }

    // ---- epilogue ----
    const int li = lane >> 2;          // 0..7
    const int lj = (lane & 3) * 2;     // 0,2,4,6
#pragma unroll
    for (int tn = 0; tn < 2; tn++) {
#pragma unroll
        for (int tm = 0; tm < 4; tm++) {
            int i0 = warp_i + tn * 16 + li;
            int j0 = warp_j + tm * 8 + lj;
            if (MODE == 1) {
                float bj0 = bias[bRow0 + j0], bj1 = bias[bRow0 + j0 + 1];
#pragma unroll
                for (int h = 0; h < 2; h++) {
                    float v0 = fmaxf(acc[tn][tm][h * 2 + 0] + bj0, 0.f);
                    float v1 = fmaxf(acc[tn][tm][h * 2 + 1] + bj1, 0.f);
                    __nv_bfloat16 h0 = __float2bfloat16(v0);
                    __nv_bfloat16 h1 = __float2bfloat16(v1);
                    __nv_bfloat162 hv; hv.x = h0; hv.y = h1;
                    __nv_bfloat162 lv;
                    lv.x = __float2bfloat16(v0 - __bfloat162float(h0));
                    lv.y = __float2bfloat16(v1 - __bfloat162float(h1));
                    size_t o = (size_t)(aRow0 + i0 + h * 8) * ost + bRow0 + j0;
                    *(__nv_bfloat162*)&outHi[o] = hv;
                    *(__nv_bfloat162*)&outLo[o] = lv;
                }
            } else {
#pragma unroll
                for (int h = 0; h < 2; h++) {
                    int i = i0 + h * 8;
                    if (i < Mreal) {
                        float bi = bias[i];
                        float2 v = make_float2(acc[tn][tm][h * 2 + 0] + bi,
                                               acc[tn][tm][h * 2 + 1] + bi);
                        *(float2*)&outF[(size_t)i * ost + bRow0 + j0] = v;
                    }
                }
            }
        }
    }
}

// ===================== attention + softmax (unchanged) =====================
#define DST 520
#define ATTN_SMEM ((80*64 + 80*128 + 64 + 128 + 64*DST) * 4)

__global__ __launch_bounds__(256)
void attn_kernel(const float* __restrict__ qf, const float* __restrict__ kf,
                 const int* __restrict__ mask,
                 float* __restrict__ attn_out, float* __restrict__ logp_out)
{
    extern __shared__ float smf[];
    float* Qs  = smf;
    float* Ks  = Qs + 80 * 64;
    float* q2s = Ks + 80 * 128;
    float* k2s = q2s + 64;
    float* Dsm = k2s + 128;

    const int b  = blockIdx.y;
    const int q0 = blockIdx.x * 64;
    const int tid = threadIdx.x;
    const int tx = tid & 15, ty = tid >> 4;

    for (int idx = tid; idx < 80 * 64; idx += 256) {
        int c = idx >> 6, qi = idx & 63;
        Qs[c * 64 + qi] = qf[(size_t)c * NQ + b * 2048 + q0 + qi];
    }
    __syncthreads();
    if (tid < 64) {
        float s = 0.f;
        for (int c = 0; c < 80; c++) { float v = Qs[c * 64 + tid]; s += v * v; }
        q2s[tid] = s;
    }

    for (int kc = 0; kc < 512; kc += 128) {
        __syncthreads();
        for (int idx = tid; idx < 80 * 128; idx += 256) {
            int c = idx >> 7, ki = idx & 127;
            Ks[c * 128 + ki] = kf[(size_t)c * NK + b * 512 + kc + ki];
        }
        __syncthreads();
        if (tid < 128) {
            float s = 0.f;
            for (int c = 0; c < 80; c++) { float v = Ks[c * 128 + tid]; s += v * v; }
            k2s[tid] = s;
        }
        float acc[4][8];
#pragma unroll
        for (int i = 0; i < 4; i++)
#pragma unroll
            for (int j = 0; j < 8; j++) acc[i][j] = 0.f;
        for (int c = 0; c < 80; c++) {
            float a[4], bb[8];
            *(float4*)(a)      = *(const float4*)&Qs[c * 64 + ty * 4];
            *(float4*)(bb)     = *(const float4*)&Ks[c * 128 + tx * 4];
            *(float4*)(bb + 4) = *(const float4*)&Ks[c * 128 + 64 + tx * 4];
#pragma unroll
            for (int i = 0; i < 4; i++)
#pragma unroll
                for (int j = 0; j < 8; j++) acc[i][j] += a[i] * bb[j];
        }
        __syncthreads();
#pragma unroll
        for (int i = 0; i < 4; i++) {
            int qi = ty * 4 + i;
#pragma unroll
            for (int j = 0; j < 8; j++) {
                int kil = (j < 4) ? (tx * 4 + j) : (64 + tx * 4 + j - 4);
                int kg = kc + kil;
                float d2 = q2s[qi] + k2s[kil] - 2.f * acc[i][j];
                float d = sqrtf(fmaxf(d2, 1e-12f));
                if (mask[b * 512 + kg] == 0) d = -FLT_MAX;
                Dsm[qi * DST + kg] = d;
            }
        }
    }
    __syncthreads();

    const size_t rowbase = ((size_t)b * 2048 + q0) * 512;
    for (int idx = tid; idx < 64 * 128; idx += 256) {
        int qi = idx >> 7;
        int c4 = (idx & 127) * 4;
        float4 v = *(const float4*)&Dsm[qi * DST + c4];
        *(float4*)&logp_out[rowbase + (size_t)qi * 512 + c4] = v;
    }

    const int warp = tid >> 5, lane = tid & 31;
    for (int r = 0; r < 8; r++) {
        int qi = warp * 8 + r;
        float vals[16];
        float mx = -FLT_MAX;
#pragma unroll
        for (int j = 0; j < 16; j++) {
            vals[j] = Dsm[qi * DST + lane + j * 32];
            mx = fmaxf(mx, vals[j]);
        }
#pragma unroll
        for (int off = 16; off; off >>= 1)
            mx = fmaxf(mx, __shfl_xor_sync(0xffffffffu, mx, off));
        float s = 0.f;
#pragma unroll
        for (int j = 0; j < 16; j++) { vals[j] = __expf(vals[j] - mx); s += vals[j]; }
#pragma unroll
        for (int off = 16; off; off >>= 1)
            s += __shfl_xor_sync(0xffffffffu, s, off);
        float inv = 1.f / s;
#pragma unroll
        for (int j = 0; j < 16; j++)
            attn_out[rowbase + (size_t)qi * 512 + lane + j * 32] = vals[j] * inv;
    }
}

// ---------------------------------------------------------------------------
extern "C" void kernel_launch(void* const* d_in, const int* in_sizes, int n_in,
                              void* d_out, int out_size)
{
    const float* queries = (const float*)d_in[0];
    const float* keys    = (const float*)d_in[1];
    const int*   mask    = (const int*)d_in[2];
    const float* kw1 = (const float*)d_in[3];
    const float* kb1 = (const float*)d_in[4];
    const float* kw2 = (const float*)d_in[5];
    const float* kb2 = (const float*)d_in[6];
    const float* qw1 = (const float*)d_in[7];
    const float* qb1 = (const float*)d_in[8];
    const float* qw2 = (const float*)d_in[9];
    const float* qb2 = (const float*)d_in[10];
    const float* qw3 = (const float*)d_in[11];
    const float* qb3 = (const float*)d_in[12];

    __nv_bfloat16 *bthi, *btlo, *w1hi, *w1lo, *hthi, *htlo, *w2hi, *w2lo;
    __nv_bfloat16 *btqhi, *btqlo, *qw1hi, *qw1lo, *q1hi, *q1lo;
    __nv_bfloat16 *qw2hi, *qw2lo, *q2hi, *q2lo, *qw3hi, *qw3lo;
    float *kf, *qf, *qb1p, *qb2p, *qb3p, *kb2p;
    cudaGetSymbolAddress((void**)&bthi, g_Bthi);
    cudaGetSymbolAddress((void**)&btlo, g_Btlo);
    cudaGetSymbolAddress((void**)&w1hi, g_w1hi);
    cudaGetSymbolAddress((void**)&w1lo, g_w1lo);
    cudaGetSymbolAddress((void**)&hthi, g_hThi);
    cudaGetSymbolAddress((void**)&htlo, g_hTlo);
    cudaGetSymbolAddress((void**)&w2hi, g_w2hi);
    cudaGetSymbolAddress((void**)&w2lo, g_w2lo);
    cudaGetSymbolAddress((void**)&btqhi, g_BtQhi);
    cudaGetSymbolAddress((void**)&btqlo, g_BtQlo);
    cudaGetSymbolAddress((void**)&qw1hi, g_qw1hi);
    cudaGetSymbolAddress((void**)&qw1lo, g_qw1lo);
    cudaGetSymbolAddress((void**)&q1hi, g_q1hi);
    cudaGetSymbolAddress((void**)&q1lo, g_q1lo);
    cudaGetSymbolAddress((void**)&qw2hi, g_qw2hi);
    cudaGetSymbolAddress((void**)&qw2lo, g_qw2lo);
    cudaGetSymbolAddress((void**)&q2hi, g_q2hi);
    cudaGetSymbolAddress((void**)&q2lo, g_q2lo);
    cudaGetSymbolAddress((void**)&qw3hi, g_qw3hi);
    cudaGetSymbolAddress((void**)&qw3lo, g_qw3lo);
    cudaGetSymbolAddress((void**)&kf, g_kf);
    cudaGetSymbolAddress((void**)&qf, g_qf);
    cudaGetSymbolAddress((void**)&qb1p, g_qb1p);
    cudaGetSymbolAddress((void**)&qb2p, g_qb2p);
    cudaGetSymbolAddress((void**)&qb3p, g_qb3p);
    cudaGetSymbolAddress((void**)&kb2p, g_kb2p);

    cudaFuncSetAttribute(mmk<1>, cudaFuncAttributeMaxDynamicSharedMemorySize, MMK_SMEM);
    cudaFuncSetAttribute(mmk<2>, cudaFuncAttributeMaxDynamicSharedMemorySize, MMK_SMEM);

    // ---- prep ----
    split_pad2<<<(1024 * 1536) / 256, 256>>>(kw1, w1hi, w1lo, 1024, 1536, 1536, 1024 * 1536);
    split_pad2<<<(128 * 1024) / 256, 256>>>(kw2, w2hi, w2lo, 80, 1024, 1024, 128 * 1024);
    split_pad2<<<(256 * 256) / 256, 256>>>(qw1, qw1hi, qw1lo, 160, 240, 256, 256 * 256);
    split_pad2<<<(128 * 256) / 256, 256>>>(qw2, qw2hi, qw2lo, 80, 160, 256, 128 * 256);
    split_pad2<<<(128 * 128) / 256, 256>>>(qw3, qw3hi, qw3lo, 80, 80, 128, 128 * 128);
    pad_bias<<<1, 256>>>(qb1, qb1p, 160, 256);
    pad_bias<<<1, 256>>>(qb2, qb2p, 80, 128);
    pad_bias<<<1, 256>>>(qb3, qb3p, 80, 128);
    pad_bias<<<1, 256>>>(kb2, kb2p, 80, 128);
    build_Bt<<<dim3(64, 8), 256>>>(keys, bthi, btlo);
    build_BtQ<<<256, 256>>>(queries, btqhi, btqlo);

    // ---- K path ----
    mmk<1><<<dim3(64, 8), 512, MMK_SMEM>>>(bthi, btlo, w1hi, w1lo, kb1,
                                           hthi, htlo, nullptr, 1536, 1024, 0);
    mmk<2><<<dim3(64, 1), 512, MMK_SMEM>>>(w2hi, w2lo, hthi, htlo, kb2p,
                                           nullptr, nullptr, kf, 1024, NK, 80);

    // ---- Q path ----
    mmk<1><<<dim3(256, 2), 512, MMK_SMEM>>>(btqhi, btqlo, qw1hi, qw1lo, qb1p,
                                            q1hi, q1lo, nullptr, 256, 256, 0);
    mmk<1><<<dim3(256, 1), 512, MMK_SMEM>>>(q1hi, q1lo, qw2hi, qw2lo, qb2p,
                                            q2hi, q2lo, nullptr, 256, 128, 0);
    mmk<2><<<dim3(256, 1), 512, MMK_SMEM>>>(qw3hi, qw3lo, q2hi, q2lo, qb3p,
                                            nullptr, nullptr, qf, 128, NQ, 80);

    // ---- attention + softmax ----
    float* attn = (float*)d_out;
    float* logp = attn + (size_t)16 * 2048 * 512;
    cudaFuncSetAttribute(attn_kernel, cudaFuncAttributeMaxDynamicSharedMemorySize, ATTN_SMEM);
    attn_kernel<<<dim3(2048 / 64, 16), 256, ATTN_SMEM>>>(qf, kf, mask, attn, logp);
}

// round 13
// speedup vs baseline: 2.6700x; 1.2459x over previous
#include <cuda_runtime.h>
#include <cuda_bf16.h>
#include <math.h>
#include <float.h>
#include <stdint.h>

#define NK 8192      // 16*512
#define NQ 32768     // 16*2048

// ---- K path buffers ----
__device__ __nv_bfloat16 g_Bthi[8192u * 1536];
__device__ __nv_bfloat16 g_Btlo[8192u * 1536];
__device__ __nv_bfloat16 g_w1hi[1024u * 1536];
__device__ __nv_bfloat16 g_w1lo[1024u * 1536];
__device__ __nv_bfloat16 g_hThi[8192u * 1024];
__device__ __nv_bfloat16 g_hTlo[8192u * 1024];
__device__ __nv_bfloat16 g_w2hi[128u * 1024];
__device__ __nv_bfloat16 g_w2lo[128u * 1024];
__device__ float g_kf[80u * NK];
// ---- Q path buffers ----
__device__ __nv_bfloat16 g_BtQhi[32768u * 256];
__device__ __nv_bfloat16 g_BtQlo[32768u * 256];
__device__ __nv_bfloat16 g_qw1hi[256u * 256];
__device__ __nv_bfloat16 g_qw1lo[256u * 256];
__device__ __nv_bfloat16 g_q1hi[32768u * 256];
__device__ __nv_bfloat16 g_q1lo[32768u * 256];
__device__ __nv_bfloat16 g_qw2hi[128u * 256];
__device__ __nv_bfloat16 g_qw2lo[128u * 256];
__device__ __nv_bfloat16 g_q2hi[32768u * 128];
__device__ __nv_bfloat16 g_q2lo[32768u * 128];
__device__ __nv_bfloat16 g_qw3hi[128u * 128];
__device__ __nv_bfloat16 g_qw3lo[128u * 128];
__device__ float g_qf[80u * NQ];
// ---- attn transposed features + norms ----
__device__ __nv_bfloat16 g_qfThi[32768u * 128];
__device__ __nv_bfloat16 g_qfTlo[32768u * 128];
__device__ __nv_bfloat16 g_kfThi[8192u * 128];
__device__ __nv_bfloat16 g_kfTlo[8192u * 128];
__device__ float g_q2n[32768];
__device__ float g_k2n[8192];
// ---- padded biases ----
__device__ float g_qb1p[256];
__device__ float g_qb2p[128];
__device__ float g_qb3p[128];
__device__ float g_kb2p[128];

// =========================== PTX helpers (sm_80+ baseline) ===========================
__device__ __forceinline__ uint32_t smem_u32(const void* p) {
    return (uint32_t)__cvta_generic_to_shared(p);
}
#define SW128(x) ((x) ^ (((x) >> 3) & 0x70))

__device__ __forceinline__ void cpa16(uint32_t dst, const void* src) {
    asm volatile("cp.async.cg.shared.global [%0], [%1], 16;\n" :: "r"(dst), "l"(src));
}
#define CP_COMMIT() asm volatile("cp.async.commit_group;\n" ::: "memory")

__device__ __forceinline__ void ldsm4(uint32_t* r, uint32_t addr) {
    asm volatile("ldmatrix.sync.aligned.m8n8.x4.shared.b16 {%0,%1,%2,%3}, [%4];"
                 : "=r"(r[0]), "=r"(r[1]), "=r"(r[2]), "=r"(r[3]) : "r"(addr));
}

__device__ __forceinline__ void mma_bf16(float* c, const uint32_t* a, const uint32_t* b) {
    asm volatile(
        "mma.sync.aligned.m16n8k16.row.col.f32.bf16.bf16.f32 "
        "{%0,%1,%2,%3}, {%4,%5,%6,%7}, {%8,%9}, {%0,%1,%2,%3};\n"
        : "+f"(c[0]), "+f"(c[1]), "+f"(c[2]), "+f"(c[3])
        : "r"(a[0]), "r"(a[1]), "r"(a[2]), "r"(a[3]), "r"(b[0]), "r"(b[1]));
}

// FFMA-only sqrt: magic rsqrt + 2 Newton iterations (rel err ~4e-6). No MUFU.
__device__ __forceinline__ float sqrt_fast(float x) {
    float y = __int_as_float(0x5f3759dfu - (__float_as_int(x) >> 1));
    y = y * fmaf(-0.5f * x * y, y, 1.5f);
    y = y * fmaf(-0.5f * x * y, y, 1.5f);
    return x * y;
}

// FFMA-only exp (exp2 range reduction + deg-5 Taylor). Valid for x <= 0; clamps at 2^-126.
__device__ __forceinline__ float exp_fast(float x) {
    float t = x * 1.4426950408889634f;
    t = fmaxf(t, -126.0f);
    float fn = t + 12582912.0f;          // 1.5 * 2^23 round-to-int trick
    float n  = fn - 12582912.0f;
    float f  = t - n;
    float p  = 1.3333558e-3f;
    p = fmaf(p, f, 9.6181291e-3f);
    p = fmaf(p, f, 5.5504109e-2f);
    p = fmaf(p, f, 2.4022651e-1f);
    p = fmaf(p, f, 6.9314718e-1f);
    p = fmaf(p, f, 1.0f);
    float sc = __int_as_float(((int)n + 127) << 23);
    return p * sc;
}

// =========================== prep kernels ===========================
__global__ void split_pad2(const float* __restrict__ in, __nv_bfloat16* __restrict__ hi,
                           __nv_bfloat16* __restrict__ lo, int R, int C, int outC, int total)
{
    int idx = blockIdx.x * 256 + threadIdx.x;
    if (idx >= total) return;
    int row = idx / outC, col = idx - row * outC;
    float v = (row < R && col < C) ? in[row * C + col] : 0.f;
    __nv_bfloat16 h = __float2bfloat16(v);
    hi[idx] = h;
    lo[idx] = __float2bfloat16(v - __bfloat162float(h));
}

__global__ void pad_bias(const float* __restrict__ in, float* __restrict__ out, int C, int outC)
{
    int i = threadIdx.x;
    if (i < outC) out[i] = (i < C) ? in[i] : 0.f;
}

__global__ __launch_bounds__(256)
void build_Bt(const float* __restrict__ keys,
              __nv_bfloat16* __restrict__ bhi, __nv_bfloat16* __restrict__ blo)
{
    __shared__ float sk[64][131];
    const int tid = threadIdx.x;
    const int nt = blockIdx.x;
    const int cc = blockIdx.y * 64;
    const int b  = nt >> 2;
    const int t0 = (nt & 3) * 128;
    const int n0 = b * 512 + t0;

    for (int idx = tid; idx < 64 * 130; idx += 256) {
        int cl = idx / 130, tt = idx - cl * 130;
        int ts = t0 + tt - 1;
        sk[cl][tt] = ((unsigned)ts < 512u)
                     ? keys[((size_t)b * 512 + cc + cl) * 512 + ts] : 0.f;
    }
    __syncthreads();
    for (int idx = tid; idx < 128 * 192; idx += 256) {
        int tl = idx / 192, r = idx - tl * 192;
        int cl = r / 3, dt = r - cl * 3;
        float v = sk[cl][tl + dt];
        __nv_bfloat16 h = __float2bfloat16(v);
        size_t o = (size_t)(n0 + tl) * 1536 + cc * 3 + r;
        bhi[o] = h;
        blo[o] = __float2bfloat16(v - __bfloat162float(h));
    }
}

__global__ __launch_bounds__(256)
void build_BtQ(const float* __restrict__ queries,
               __nv_bfloat16* __restrict__ bhi, __nv_bfloat16* __restrict__ blo)
{
    __shared__ float sk[80][131];
    const int tid = threadIdx.x;
    const int nt = blockIdx.x;
    const int b  = nt >> 4;
    const int t0 = (nt & 15) * 128;
    const int n0 = b * 2048 + t0;

    for (int idx = tid; idx < 80 * 130; idx += 256) {
        int cl = idx / 130, tt = idx - cl * 130;
        int ts = t0 + tt - 1;
        sk[cl][tt] = ((unsigned)ts < 2048u)
                     ? queries[((size_t)b * 80 + cl) * 2048 + ts] : 0.f;
    }
    __syncthreads();
    for (int idx = tid; idx < 128 * 256; idx += 256) {
        int tl = idx >> 8, r = idx & 255;
        float v = 0.f;
        if (r < 240) {
            int cl = r / 3, dt = r - cl * 3;
            v = sk[cl][tl + dt];
        }
        __nv_bfloat16 h = __float2bfloat16(v);
        size_t o = (size_t)(n0 + tl) * 256 + r;
        bhi[o] = h;
        blo[o] = __float2bfloat16(v - __bfloat162float(h));
    }
}

// Transpose [80][N] fp32 -> [n][128] bf16 hi/lo (c padded to 128) + fp32 norms.
__global__ __launch_bounds__(256)
void cvtT(const float* __restrict__ src, int N,
          __nv_bfloat16* __restrict__ dhi, __nv_bfloat16* __restrict__ dlo,
          float* __restrict__ nrm)
{
    __shared__ float s[80][132];
    const int tid = threadIdx.x;
    const int n0 = blockIdx.x * 128;
    for (int q = tid; q < 80 * 32; q += 256) {
        int c = q >> 5, j = (q & 31) * 4;
        *(float4*)&s[c][j] = *(const float4*)&src[(size_t)c * N + n0 + j];
    }
    __syncthreads();
    for (int idx = tid; idx < 128 * 128; idx += 256) {
        int nl = idx >> 7, c = idx & 127;
        float v = (c < 80) ? s[c][nl] : 0.f;
        __nv_bfloat16 h = __float2bfloat16(v);
        size_t o = (size_t)(n0 + nl) * 128 + c;
        dhi[o] = h;
        dlo[o] = __float2bfloat16(v - __bfloat162float(h));
    }
    if (tid < 128) {
        float sum = 0.f;
        for (int c = 0; c < 80; c++) { float v = s[c][tid]; sum += v * v; }
        nrm[n0 + tid] = sum;
    }
}

// ===================== mma.sync bf16x3 GEMM (unchanged from R12) =====================
#define MMK_SMEM 131072

template<int MODE>
__global__ __launch_bounds__(512)
void mmk(const __nv_bfloat16* __restrict__ aHi, const __nv_bfloat16* __restrict__ aLo,
         const __nv_bfloat16* __restrict__ bHi, const __nv_bfloat16* __restrict__ bLo,
         const float* __restrict__ bias,
         __nv_bfloat16* __restrict__ outHi, __nv_bfloat16* __restrict__ outLo,
         float* __restrict__ outF, int Kdim, int ost, int Mreal)
{
    extern __shared__ __align__(1024) char smx[];
    const int tid  = threadIdx.x;
    const int wid  = tid >> 5, lane = tid & 31;
    const int nCh  = Kdim >> 6;

    const int aRow0 = (MODE == 1) ? blockIdx.x * 128 : 0;
    const int bRow0 = (MODE == 1) ? blockIdx.y * 128 : blockIdx.x * 128;

    const int warp_i = (wid >> 2) * 32;
    const int warp_j = (wid & 3) * 32;

    const uint32_t sbase = smem_u32(smx);
    const uint32_t stA[2] = { sbase, sbase + 65536u };

    auto load_chunk = [&](int c, int s) {
        const uint32_t base = stA[s];
        const size_t cb = (size_t)c * 64;
#pragma unroll
        for (int it = 0; it < 8; it++) {
            int idx = tid + it * 512;
            int mat = idx >> 10;
            int r   = (idx & 1023) >> 3;
            int g   = idx & 7;
            const __nv_bfloat16* srcm =
                (mat == 0) ? aHi : (mat == 1) ? aLo : (mat == 2) ? bHi : bLo;
            int row0 = (mat < 2) ? aRow0 : bRow0;
            cpa16(base + mat * 16384u + SW128((r << 7) + (g << 4)),
                  srcm + (size_t)(row0 + r) * Kdim + cb + g * 8);
        }
    };

    load_chunk(0, 0); CP_COMMIT();
    load_chunk(1, 1); CP_COMMIT();

    float acc[2][4][4];
#pragma unroll
    for (int a = 0; a < 2; a++)
#pragma unroll
        for (int b = 0; b < 4; b++)
#pragma unroll
            for (int r = 0; r < 4; r++) acc[a][b][r] = 0.f;

    for (int c = 0; c < nCh; c++) {
        const int s = c & 1;
        if (c + 1 < nCh) asm volatile("cp.async.wait_group 1;" ::: "memory");
        else             asm volatile("cp.async.wait_group 0;" ::: "memory");
        __syncthreads();

        const uint32_t A_hi = stA[s], A_lo = stA[s] + 16384u;
        const uint32_t B_hi = stA[s] + 32768u, B_lo = stA[s] + 49152u;

#pragma unroll
        for (int ks = 0; ks < 4; ks++) {
            const int kb = ks * 32;
            uint32_t ah[2][4], al[2][4], bh[4][2], bl[4][2];
            {
                const int g = lane >> 3;
                const int arow = (lane & 7) + ((g & 1) << 3);
                const int akc  = kb + ((g >> 1) << 4);
#pragma unroll
                for (int tn = 0; tn < 2; tn++) {
                    uint32_t off = SW128(((warp_i + tn * 16 + arow) << 7) + akc);
                    ldsm4(ah[tn], A_hi + off);
                    ldsm4(al[tn], A_lo + off);
                }
                const int brow = (lane & 7) + ((g >> 1) << 3);
                const int bkc  = kb + ((g & 1) << 4);
#pragma unroll
                for (int p = 0; p < 2; p++) {
                    uint32_t off = SW128(((warp_j + p * 16 + brow) << 7) + bkc);
                    uint32_t r4[4];
                    ldsm4(r4, B_hi + off);
                    bh[p * 2][0] = r4[0]; bh[p * 2][1] = r4[1];
                    bh[p * 2 + 1][0] = r4[2]; bh[p * 2 + 1][1] = r4[3];
                    ldsm4(r4, B_lo + off);
                    bl[p * 2][0] = r4[0]; bl[p * 2][1] = r4[1];
                    bl[p * 2 + 1][0] = r4[2]; bl[p * 2 + 1][1] = r4[3];
                }
            }
#pragma unroll
            for (int tn = 0; tn < 2; tn++)
#pragma unroll
                for (int tm = 0; tm < 4; tm++) {
                    mma_bf16(acc[tn][tm], ah[tn], bh[tm]);
                    mma_bf16(acc[tn][tm], al[tn], bh[tm]);
                    mma_bf16(acc[tn][tm], ah[tn], bl[tm]);
                }
        }
        __syncthreads();
        if (c + 2 < nCh) { load_chunk(c + 2, s); CP_COMMIT(); }
    }

    const int li = lane >> 2;
    const int lj = (lane & 3) * 2;
#pragma unroll
    for (int tn = 0; tn < 2; tn++) {
#pragma unroll
        for (int tm = 0; tm < 4; tm++) {
            int i0 = warp_i + tn * 16 + li;
            int j0 = warp_j + tm * 8 + lj;
            if (MODE == 1) {
                float bj0 = bias[bRow0 + j0], bj1 = bias[bRow0 + j0 + 1];
#pragma unroll
                for (int h = 0; h < 2; h++) {
                    float v0 = fmaxf(acc[tn][tm][h * 2 + 0] + bj0, 0.f);
                    float v1 = fmaxf(acc[tn][tm][h * 2 + 1] + bj1, 0.f);
                    __nv_bfloat16 h0 = __float2bfloat16(v0);
                    __nv_bfloat16 h1 = __float2bfloat16(v1);
                    __nv_bfloat162 hv; hv.x = h0; hv.y = h1;
                    __nv_bfloat162 lv;
                    lv.x = __float2bfloat16(v0 - __bfloat162float(h0));
                    lv.y = __float2bfloat16(v1 - __bfloat162float(h1));
                    size_t o = (size_t)(aRow0 + i0 + h * 8) * ost + bRow0 + j0;
                    *(__nv_bfloat162*)&outHi[o] = hv;
                    *(__nv_bfloat162*)&outLo[o] = lv;
                }
            } else {
#pragma unroll
                for (int h = 0; h < 2; h++) {
                    int i = i0 + h * 8;
                    if (i < Mreal) {
                        float bi = bias[i];
                        float2 v = make_float2(acc[tn][tm][h * 2 + 0] + bi,
                                               acc[tn][tm][h * 2 + 1] + bi);
                        *(float2*)&outF[(size_t)i * ost + bRow0 + j0] = v;
                    }
                }
            }
        }
    }
}

// ===================== attention: HMMA QK + FFMA sqrt/exp softmax =====================
// Block: 32 q rows x 512 k, one batch. 256 threads (8 warps).
// smem: Q pair (2 tiles x 32r x 128B) x2 = 16KB @0
//       K stages: 2 x (hi 32KB + lo 32KB)   = 128KB @16384
//       Dsm [32][516] fp32                  = 66048 @147456
//       q2s[32] @213504, k2s[512] @213632, mask[512] @215680  -> total 217728
#define ATT_SMEM 217728
#define DSTA 516

__global__ __launch_bounds__(256)
void attn_kernel(const __nv_bfloat16* __restrict__ qhi, const __nv_bfloat16* __restrict__ qlo,
                 const __nv_bfloat16* __restrict__ khi, const __nv_bfloat16* __restrict__ klo,
                 const float* __restrict__ q2g, const float* __restrict__ k2g,
                 const int* __restrict__ mask,
                 float* __restrict__ attn_out, float* __restrict__ logp_out)
{
    extern __shared__ __align__(1024) char smraw[];
    const uint32_t sbase = smem_u32(smraw);
    const uint32_t QHI = sbase, QLO = sbase + 8192u;
    const uint32_t KST = sbase + 16384u;           // + s*65536; lo at +32768
    float* Dsm   = (float*)(smraw + 147456);
    float* q2s   = (float*)(smraw + 213504);
    float* k2s   = (float*)(smraw + 213632);
    int*   maskS = (int*)  (smraw + 215680);

    const int b   = blockIdx.y;
    const int q0  = blockIdx.x * 32;
    const int tid = threadIdx.x;
    const int wid = tid >> 5, lane = tid & 31;
    const int nq0 = b * 2048 + q0;
    const int nk0 = b * 512;

    // ---- load Q tiles (cp.async) ----
#pragma unroll
    for (int it = 0; it < 4; it++) {
        int idx = tid + it * 256;            // 0..1023
        int half = idx >> 9;                 // 0 hi, 1 lo
        int rem  = idx & 511;
        int h    = rem >> 8;
        int rr   = (rem >> 3) & 31;
        int g    = rem & 7;
        const __nv_bfloat16* src = (half ? qlo : qhi);
        cpa16((half ? QLO : QHI) + h * 4096u + SW128((rr << 7) + (g << 4)),
              src + (size_t)(nq0 + rr) * 128 + h * 64 + g * 8);
    }
    // K chunk loader
    auto load_k = [&](int kc, int s) {
        const uint32_t base = KST + (uint32_t)s * 65536u;
#pragma unroll
        for (int it = 0; it < 16; it++) {
            int idx = tid + it * 256;        // 0..4095
            int half = idx >> 11;
            int rem  = idx & 2047;
            int h    = rem >> 10;
            int rr   = (rem >> 3) & 127;
            int g    = rem & 7;
            const __nv_bfloat16* src = (half ? klo : khi);
            cpa16(base + half * 32768u + h * 16384u + SW128((rr << 7) + (g << 4)),
                  src + (size_t)(nk0 + kc * 128 + rr) * 128 + h * 64 + g * 8);
        }
    };
    load_k(0, 0); CP_COMMIT();
    load_k(1, 1); CP_COMMIT();

    // norms + mask into smem (regular loads)
    if (tid < 32)  q2s[tid] = q2g[nq0 + tid];
    for (int i = tid; i < 512; i += 256) {
        k2s[i]   = k2g[nk0 + i];
        maskS[i] = mask[nk0 + i];
    }

    const int li = lane >> 2;
    const int lj = (lane & 3) * 2;
    const int wj = wid * 16;

    for (int kc = 0; kc < 4; kc++) {
        const int s = kc & 1;
        if (kc + 1 < 4) asm volatile("cp.async.wait_group 1;" ::: "memory");
        else            asm volatile("cp.async.wait_group 0;" ::: "memory");
        __syncthreads();

        float acc[2][2][4];
#pragma unroll
        for (int a = 0; a < 2; a++)
#pragma unroll
            for (int c2 = 0; c2 < 2; c2++)
#pragma unroll
                for (int r = 0; r < 4; r++) acc[a][c2][r] = 0.f;

        const uint32_t KB = KST + (uint32_t)s * 65536u;
#pragma unroll
        for (int ks = 0; ks < 8; ks++) {
            const int h  = ks >> 2;
            const int kb = (ks & 3) * 32;
            const int g  = lane >> 3;
            uint32_t ah[2][4], al[2][4], bh[2][2], bl[2][2];
            {
                const int arow = (lane & 7) + ((g & 1) << 3);
                const int akc  = kb + ((g >> 1) << 4);
#pragma unroll
                for (int tn = 0; tn < 2; tn++) {
                    uint32_t off = (uint32_t)h * 4096u + SW128(((tn * 16 + arow) << 7) + akc);
                    ldsm4(ah[tn], QHI + off);
                    ldsm4(al[tn], QLO + off);
                }
                const int brow = (lane & 7) + ((g >> 1) << 3);
                const int bkc  = kb + ((g & 1) << 4);
                uint32_t off = (uint32_t)h * 16384u + SW128(((wj + brow) << 7) + bkc);
                uint32_t r4[4];
                ldsm4(r4, KB + off);
                bh[0][0] = r4[0]; bh[0][1] = r4[1]; bh[1][0] = r4[2]; bh[1][1] = r4[3];
                ldsm4(r4, KB + 32768u + off);
                bl[0][0] = r4[0]; bl[0][1] = r4[1]; bl[1][0] = r4[2]; bl[1][1] = r4[3];
            }
#pragma unroll
            for (int tn = 0; tn < 2; tn++)
#pragma unroll
                for (int tm = 0; tm < 2; tm++) {
                    mma_bf16(acc[tn][tm], ah[tn], bh[tm]);
                    mma_bf16(acc[tn][tm], al[tn], bh[tm]);
                    mma_bf16(acc[tn][tm], ah[tn], bl[tm]);
                }
        }

        // epilogue: d = sqrt(max(q2+k2-2qk,1e-12)), mask, -> Dsm
#pragma unroll
        for (int tn = 0; tn < 2; tn++)
#pragma unroll
            for (int tm = 0; tm < 2; tm++)
#pragma unroll
                for (int hh = 0; hh < 2; hh++) {
                    int i  = tn * 16 + hh * 8 + li;
                    int kg = kc * 128 + wj + tm * 8 + lj;
                    float q2v = q2s[i];
                    float d0 = q2v + k2s[kg]     - 2.f * acc[tn][tm][hh * 2 + 0];
                    float d1 = q2v + k2s[kg + 1] - 2.f * acc[tn][tm][hh * 2 + 1];
                    d0 = sqrt_fast(fmaxf(d0, 1e-12f));
                    d1 = sqrt_fast(fmaxf(d1, 1e-12f));
                    if (maskS[kg]     == 0) d0 = -FLT_MAX;
                    if (maskS[kg + 1] == 0) d1 = -FLT_MAX;
                    *(float2*)&Dsm[i * DSTA + kg] = make_float2(d0, d1);
                }
        __syncthreads();
        if (kc + 2 < 4) { load_k(kc + 2, s); CP_COMMIT(); }
    }

    // ---- logp write (coalesced float4) ----
    const size_t rowbase = ((size_t)b * 2048 + q0) * 512;
#pragma unroll
    for (int it = 0; it < 16; it++) {
        int idx = tid + it * 256;            // 0..4095
        int qi = idx >> 7;
        int c4 = (idx & 127) * 4;
        float4 v = *(const float4*)&Dsm[qi * DSTA + c4];
        *(float4*)&logp_out[rowbase + (size_t)qi * 512 + c4] = v;
    }

    // ---- softmax (FFMA exp) : warp w rows w*4..w*4+3 ----
    for (int r = 0; r < 4; r++) {
        int qi = wid * 4 + r;
        float vals[16];
        float mx = -FLT_MAX;
#pragma unroll
        for (int j = 0; j < 16; j++) {
            vals[j] = Dsm[qi * DSTA + lane + j * 32];
            mx = fmaxf(mx, vals[j]);
        }
#pragma unroll
        for (int off = 16; off; off >>= 1)
            mx = fmaxf(mx, __shfl_xor_sync(0xffffffffu, mx, off));
        float s = 0.f;
#pragma unroll
        for (int j = 0; j < 16; j++) { vals[j] = exp_fast(vals[j] - mx); s += vals[j]; }
#pragma unroll
        for (int off = 16; off; off >>= 1)
            s += __shfl_xor_sync(0xffffffffu, s, off);
        float inv = 1.f / s;
#pragma unroll
        for (int j = 0; j < 16; j++)
            attn_out[rowbase + (size_t)qi * 512 + lane + j * 32] = vals[j] * inv;
    }
}

// ---------------------------------------------------------------------------
extern "C" void kernel_launch(void* const* d_in, const int* in_sizes, int n_in,
                              void* d_out, int out_size)
{
    const float* queries = (const float*)d_in[0];
    const float* keys    = (const float*)d_in[1];
    const int*   mask    = (const int*)d_in[2];
    const float* kw1 = (const float*)d_in[3];
    const float* kb1 = (const float*)d_in[4];
    const float* kw2 = (const float*)d_in[5];
    const float* kb2 = (const float*)d_in[6];
    const float* qw1 = (const float*)d_in[7];
    const float* qb1 = (const float*)d_in[8];
    const float* qw2 = (const float*)d_in[9];
    const float* qb2 = (const float*)d_in[10];
    const float* qw3 = (const float*)d_in[11];
    const float* qb3 = (const float*)d_in[12];

    __nv_bfloat16 *bthi, *btlo, *w1hi, *w1lo, *hthi, *htlo, *w2hi, *w2lo;
    __nv_bfloat16 *btqhi, *btqlo, *qw1hi, *qw1lo, *q1hi, *q1lo;
    __nv_bfloat16 *qw2hi, *qw2lo, *q2hi, *q2lo, *qw3hi, *qw3lo;
    __nv_bfloat16 *qfthi, *qftlo, *kfthi, *kftlo;
    float *kf, *qf, *qb1p, *qb2p, *qb3p, *kb2p, *q2n, *k2n;
    cudaGetSymbolAddress((void**)&bthi, g_Bthi);
    cudaGetSymbolAddress((void**)&btlo, g_Btlo);
    cudaGetSymbolAddress((void**)&w1hi, g_w1hi);
    cudaGetSymbolAddress((void**)&w1lo, g_w1lo);
    cudaGetSymbolAddress((void**)&hthi, g_hThi);
    cudaGetSymbolAddress((void**)&htlo, g_hTlo);
    cudaGetSymbolAddress((void**)&w2hi, g_w2hi);
    cudaGetSymbolAddress((void**)&w2lo, g_w2lo);
    cudaGetSymbolAddress((void**)&btqhi, g_BtQhi);
    cudaGetSymbolAddress((void**)&btqlo, g_BtQlo);
    cudaGetSymbolAddress((void**)&qw1hi, g_qw1hi);
    cudaGetSymbolAddress((void**)&qw1lo, g_qw1lo);
    cudaGetSymbolAddress((void**)&q1hi, g_q1hi);
    cudaGetSymbolAddress((void**)&q1lo, g_q1lo);
    cudaGetSymbolAddress((void**)&qw2hi, g_qw2hi);
    cudaGetSymbolAddress((void**)&qw2lo, g_qw2lo);
    cudaGetSymbolAddress((void**)&q2hi, g_q2hi);
    cudaGetSymbolAddress((void**)&q2lo, g_q2lo);
    cudaGetSymbolAddress((void**)&qw3hi, g_qw3hi);
    cudaGetSymbolAddress((void**)&qw3lo, g_qw3lo);
    cudaGetSymbolAddress((void**)&qfthi, g_qfThi);
    cudaGetSymbolAddress((void**)&qftlo, g_qfTlo);
    cudaGetSymbolAddress((void**)&kfthi, g_kfThi);
    cudaGetSymbolAddress((void**)&kftlo, g_kfTlo);
    cudaGetSymbolAddress((void**)&kf, g_kf);
    cudaGetSymbolAddress((void**)&qf, g_qf);
    cudaGetSymbolAddress((void**)&qb1p, g_qb1p);
    cudaGetSymbolAddress((void**)&qb2p, g_qb2p);
    cudaGetSymbolAddress((void**)&qb3p, g_qb3p);
    cudaGetSymbolAddress((void**)&kb2p, g_kb2p);
    cudaGetSymbolAddress((void**)&q2n, g_q2n);
    cudaGetSymbolAddress((void**)&k2n, g_k2n);

    cudaFuncSetAttribute(mmk<1>, cudaFuncAttributeMaxDynamicSharedMemorySize, MMK_SMEM);
    cudaFuncSetAttribute(mmk<2>, cudaFuncAttributeMaxDynamicSharedMemorySize, MMK_SMEM);
    cudaFuncSetAttribute(attn_kernel, cudaFuncAttributeMaxDynamicSharedMemorySize, ATT_SMEM);

    // ---- prep ----
    split_pad2<<<(1024 * 1536) / 256, 256>>>(kw1, w1hi, w1lo, 1024, 1536, 1536, 1024 * 1536);
    split_pad2<<<(128 * 1024) / 256, 256>>>(kw2, w2hi, w2lo, 80, 1024, 1024, 128 * 1024);
    split_pad2<<<(256 * 256) / 256, 256>>>(qw1, qw1hi, qw1lo, 160, 240, 256, 256 * 256);
    split_pad2<<<(128 * 256) / 256, 256>>>(qw2, qw2hi, qw2lo, 80, 160, 256, 128 * 256);
    split_pad2<<<(128 * 128) / 256, 256>>>(qw3, qw3hi, qw3lo, 80, 80, 128, 128 * 128);
    pad_bias<<<1, 256>>>(qb1, qb1p, 160, 256);
    pad_bias<<<1, 256>>>(qb2, qb2p, 80, 128);
    pad_bias<<<1, 256>>>(qb3, qb3p, 80, 128);
    pad_bias<<<1, 256>>>(kb2, kb2p, 80, 128);
    build_Bt<<<dim3(64, 8), 256>>>(keys, bthi, btlo);
    build_BtQ<<<256, 256>>>(queries, btqhi, btqlo);

    // ---- K path ----
    mmk<1><<<dim3(64, 8), 512, MMK_SMEM>>>(bthi, btlo, w1hi, w1lo, kb1,
                                           hthi, htlo, nullptr, 1536, 1024, 0);
    mmk<2><<<dim3(64, 1), 512, MMK_SMEM>>>(w2hi, w2lo, hthi, htlo, kb2p,
                                           nullptr, nullptr, kf, 1024, NK, 80);

    // ---- Q path ----
    mmk<1><<<dim3(256, 2), 512, MMK_SMEM>>>(btqhi, btqlo, qw1hi, qw1lo, qb1p,
                                            q1hi, q1lo, nullptr, 256, 256, 0);
    mmk<1><<<dim3(256, 1), 512, MMK_SMEM>>>(q1hi, q1lo, qw2hi, qw2lo, qb2p,
                                            q2hi, q2lo, nullptr, 256, 128, 0);
    mmk<2><<<dim3(256, 1), 512, MMK_SMEM>>>(qw3hi, qw3lo, q2hi, q2lo, qb3p,
                                            nullptr, nullptr, qf, 128, NQ, 80);

    // ---- transpose/split features + norms for attention ----
    cvtT<<<NQ / 128, 256>>>(qf, NQ, qfthi, qftlo, q2n);
    cvtT<<<NK / 128, 256>>>(kf, NK, kfthi, kftlo, k2n);

    // ---- attention + softmax ----
    float* attn = (float*)d_out;
    float* logp = attn + (size_t)16 * 2048 * 512;
    attn_kernel<<<dim3(2048 / 32, 16), 256, ATT_SMEM>>>(qfthi, qftlo, kfthi, kftlo,
                                                        q2n, k2n, mask, attn, logp);
}

// round 14
// speedup vs baseline: 2.7004x; 1.0114x over previous
#include <cuda_runtime.h>
#include <cuda_bf16.h>
#include <math.h>
#include <float.h>
#include <stdint.h>

#define NK 8192      // 16*512
#define NQ 32768     // 16*2048

// ---- K path buffers ----
__device__ __nv_bfloat16 g_Bthi[8192u * 1536];
__device__ __nv_bfloat16 g_Btlo[8192u * 1536];
__device__ __nv_bfloat16 g_w1hi[1024u * 1536];
__device__ __nv_bfloat16 g_w1lo[1024u * 1536];
__device__ __nv_bfloat16 g_hThi[8192u * 1024];
__device__ __nv_bfloat16 g_hTlo[8192u * 1024];
__device__ __nv_bfloat16 g_w2hi[128u * 1024];
__device__ __nv_bfloat16 g_w2lo[128u * 1024];
__device__ float g_kf[80u * NK];
// ---- Q path buffers ----
__device__ __nv_bfloat16 g_BtQhi[32768u * 256];
__device__ __nv_bfloat16 g_BtQlo[32768u * 256];
__device__ __nv_bfloat16 g_qw1hi[256u * 256];
__device__ __nv_bfloat16 g_qw1lo[256u * 256];
__device__ __nv_bfloat16 g_q1hi[32768u * 256];
__device__ __nv_bfloat16 g_q1lo[32768u * 256];
__device__ __nv_bfloat16 g_qw2hi[128u * 256];
__device__ __nv_bfloat16 g_qw2lo[128u * 256];
__device__ __nv_bfloat16 g_q2hi[32768u * 128];
__device__ __nv_bfloat16 g_q2lo[32768u * 128];
__device__ __nv_bfloat16 g_qw3hi[128u * 128];
__device__ __nv_bfloat16 g_qw3lo[128u * 128];
__device__ float g_qf[80u * NQ];
// ---- attn transposed features + norms ----
__device__ __nv_bfloat16 g_qfThi[32768u * 128];
__device__ __nv_bfloat16 g_qfTlo[32768u * 128];
__device__ __nv_bfloat16 g_kfThi[8192u * 128];
__device__ __nv_bfloat16 g_kfTlo[8192u * 128];
__device__ float g_q2n[32768];
__device__ float g_k2n[8192];
// ---- padded biases ----
__device__ float g_qb1p[256];
__device__ float g_qb2p[128];
__device__ float g_qb3p[128];
__device__ float g_kb2p[128];

// =========================== PTX helpers (sm_80+ baseline) ===========================
__device__ __forceinline__ uint32_t smem_u32(const void* p) {
    return (uint32_t)__cvta_generic_to_shared(p);
}
#define SW128(x) ((x) ^ (((x) >> 3) & 0x70))

__device__ __forceinline__ void cpa16(uint32_t dst, const void* src) {
    asm volatile("cp.async.cg.shared.global [%0], [%1], 16;\n" :: "r"(dst), "l"(src));
}
#define CP_COMMIT() asm volatile("cp.async.commit_group;\n" ::: "memory")

__device__ __forceinline__ void ldsm4(uint32_t* r, uint32_t addr) {
    asm volatile("ldmatrix.sync.aligned.m8n8.x4.shared.b16 {%0,%1,%2,%3}, [%4];"
                 : "=r"(r[0]), "=r"(r[1]), "=r"(r[2]), "=r"(r[3]) : "r"(addr));
}

__device__ __forceinline__ void mma_bf16(float* c, const uint32_t* a, const uint32_t* b) {
    asm volatile(
        "mma.sync.aligned.m16n8k16.row.col.f32.bf16.bf16.f32 "
        "{%0,%1,%2,%3}, {%4,%5,%6,%7}, {%8,%9}, {%0,%1,%2,%3};\n"
        : "+f"(c[0]), "+f"(c[1]), "+f"(c[2]), "+f"(c[3])
        : "r"(a[0]), "r"(a[1]), "r"(a[2]), "r"(a[3]), "r"(b[0]), "r"(b[1]));
}

// FFMA-only sqrt: magic rsqrt + 2 Newton iterations (rel err ~4e-6). No MUFU.
__device__ __forceinline__ float sqrt_fast(float x) {
    float y = __int_as_float(0x5f3759dfu - (__float_as_int(x) >> 1));
    y = y * fmaf(-0.5f * x * y, y, 1.5f);
    y = y * fmaf(-0.5f * x * y, y, 1.5f);
    return x * y;
}

// FFMA-only exp (exp2 range reduction + deg-5 poly). Valid for x <= 0.
__device__ __forceinline__ float exp_fast(float x) {
    float t = x * 1.4426950408889634f;
    t = fmaxf(t, -126.0f);
    float fn = t + 12582912.0f;
    float n  = fn - 12582912.0f;
    float f  = t - n;
    float p  = 1.3333558e-3f;
    p = fmaf(p, f, 9.6181291e-3f);
    p = fmaf(p, f, 5.5504109e-2f);
    p = fmaf(p, f, 2.4022651e-1f);
    p = fmaf(p, f, 6.9314718e-1f);
    p = fmaf(p, f, 1.0f);
    float sc = __int_as_float(((int)n + 127) << 23);
    return p * sc;
}

// =========================== prep kernels ===========================
__global__ void split_pad2(const float* __restrict__ in, __nv_bfloat16* __restrict__ hi,
                           __nv_bfloat16* __restrict__ lo, int R, int C, int outC, int total)
{
    int idx = blockIdx.x * 256 + threadIdx.x;
    if (idx >= total) return;
    int row = idx / outC, col = idx - row * outC;
    float v = (row < R && col < C) ? in[row * C + col] : 0.f;
    __nv_bfloat16 h = __float2bfloat16(v);
    hi[idx] = h;
    lo[idx] = __float2bfloat16(v - __bfloat162float(h));
}

__global__ void pad_bias(const float* __restrict__ in, float* __restrict__ out, int C, int outC)
{
    int i = threadIdx.x;
    if (i < outC) out[i] = (i < C) ? in[i] : 0.f;
}

__global__ __launch_bounds__(256)
void build_Bt(const float* __restrict__ keys,
              __nv_bfloat16* __restrict__ bhi, __nv_bfloat16* __restrict__ blo)
{
    __shared__ float sk[64][131];
    const int tid = threadIdx.x;
    const int nt = blockIdx.x;
    const int cc = blockIdx.y * 64;
    const int b  = nt >> 2;
    const int t0 = (nt & 3) * 128;
    const int n0 = b * 512 + t0;

    for (int idx = tid; idx < 64 * 130; idx += 256) {
        int cl = idx / 130, tt = idx - cl * 130;
        int ts = t0 + tt - 1;
        sk[cl][tt] = ((unsigned)ts < 512u)
                     ? keys[((size_t)b * 512 + cc + cl) * 512 + ts] : 0.f;
    }
    __syncthreads();
    for (int idx = tid; idx < 128 * 192; idx += 256) {
        int tl = idx / 192, r = idx - tl * 192;
        int cl = r / 3, dt = r - cl * 3;
        float v = sk[cl][tl + dt];
        __nv_bfloat16 h = __float2bfloat16(v);
        size_t o = (size_t)(n0 + tl) * 1536 + cc * 3 + r;
        bhi[o] = h;
        blo[o] = __float2bfloat16(v - __bfloat162float(h));
    }
}

__global__ __launch_bounds__(256)
void build_BtQ(const float* __restrict__ queries,
               __nv_bfloat16* __restrict__ bhi, __nv_bfloat16* __restrict__ blo)
{
    __shared__ float sk[80][131];
    const int tid = threadIdx.x;
    const int nt = blockIdx.x;
    const int b  = nt >> 4;
    const int t0 = (nt & 15) * 128;
    const int n0 = b * 2048 + t0;

    for (int idx = tid; idx < 80 * 130; idx += 256) {
        int cl = idx / 130, tt = idx - cl * 130;
        int ts = t0 + tt - 1;
        sk[cl][tt] = ((unsigned)ts < 2048u)
                     ? queries[((size_t)b * 80 + cl) * 2048 + ts] : 0.f;
    }
    __syncthreads();
    for (int idx = tid; idx < 128 * 256; idx += 256) {
        int tl = idx >> 8, r = idx & 255;
        float v = 0.f;
        if (r < 240) {
            int cl = r / 3, dt = r - cl * 3;
            v = sk[cl][tl + dt];
        }
        __nv_bfloat16 h = __float2bfloat16(v);
        size_t o = (size_t)(n0 + tl) * 256 + r;
        bhi[o] = h;
        blo[o] = __float2bfloat16(v - __bfloat162float(h));
    }
}

// Transpose [80][N] fp32 -> [n][128] bf16 hi/lo (c padded to 128) + fp32 norms.
__global__ __launch_bounds__(256)
void cvtT(const float* __restrict__ src, int N,
          __nv_bfloat16* __restrict__ dhi, __nv_bfloat16* __restrict__ dlo,
          float* __restrict__ nrm)
{
    __shared__ float s[80][132];
    const int tid = threadIdx.x;
    const int n0 = blockIdx.x * 128;
    for (int q = tid; q < 80 * 32; q += 256) {
        int c = q >> 5, j = (q & 31) * 4;
        *(float4*)&s[c][j] = *(const float4*)&src[(size_t)c * N + n0 + j];
    }
    __syncthreads();
    for (int idx = tid; idx < 128 * 128; idx += 256) {
        int nl = idx >> 7, c = idx & 127;
        float v = (c < 80) ? s[c][nl] : 0.f;
        __nv_bfloat16 h = __float2bfloat16(v);
        size_t o = (size_t)(n0 + nl) * 128 + c;
        dhi[o] = h;
        dlo[o] = __float2bfloat16(v - __bfloat162float(h));
    }
    if (tid < 128) {
        float sum = 0.f;
        for (int c = 0; c < 80; c++) { float v = s[c][tid]; sum += v * v; }
        nrm[n0 + tid] = sum;
    }
}

// ===================== mma.sync bf16x3 GEMM (unchanged) =====================
#define MMK_SMEM 131072

template<int MODE>
__global__ __launch_bounds__(512)
void mmk(const __nv_bfloat16* __restrict__ aHi, const __nv_bfloat16* __restrict__ aLo,
         const __nv_bfloat16* __restrict__ bHi, const __nv_bfloat16* __restrict__ bLo,
         const float* __restrict__ bias,
         __nv_bfloat16* __restrict__ outHi, __nv_bfloat16* __restrict__ outLo,
         float* __restrict__ outF, int Kdim, int ost, int Mreal)
{
    extern __shared__ __align__(1024) char smx[];
    const int tid  = threadIdx.x;
    const int wid  = tid >> 5, lane = tid & 31;
    const int nCh  = Kdim >> 6;

    const int aRow0 = (MODE == 1) ? blockIdx.x * 128 : 0;
    const int bRow0 = (MODE == 1) ? blockIdx.y * 128 : blockIdx.x * 128;

    const int warp_i = (wid >> 2) * 32;
    const int warp_j = (wid & 3) * 32;

    const uint32_t sbase = smem_u32(smx);
    const uint32_t stA[2] = { sbase, sbase + 65536u };

    auto load_chunk = [&](int c, int s) {
        const uint32_t base = stA[s];
        const size_t cb = (size_t)c * 64;
#pragma unroll
        for (int it = 0; it < 8; it++) {
            int idx = tid + it * 512;
            int mat = idx >> 10;
            int r   = (idx & 1023) >> 3;
            int g   = idx & 7;
            const __nv_bfloat16* srcm =
                (mat == 0) ? aHi : (mat == 1) ? aLo : (mat == 2) ? bHi : bLo;
            int row0 = (mat < 2) ? aRow0 : bRow0;
            cpa16(base + mat * 16384u + SW128((r << 7) + (g << 4)),
                  srcm + (size_t)(row0 + r) * Kdim + cb + g * 8);
        }
    };

    load_chunk(0, 0); CP_COMMIT();
    load_chunk(1, 1); CP_COMMIT();

    float acc[2][4][4];
#pragma unroll
    for (int a = 0; a < 2; a++)
#pragma unroll
        for (int b = 0; b < 4; b++)
#pragma unroll
            for (int r = 0; r < 4; r++) acc[a][b][r] = 0.f;

    for (int c = 0; c < nCh; c++) {
        const int s = c & 1;
        if (c + 1 < nCh) asm volatile("cp.async.wait_group 1;" ::: "memory");
        else             asm volatile("cp.async.wait_group 0;" ::: "memory");
        __syncthreads();

        const uint32_t A_hi = stA[s], A_lo = stA[s] + 16384u;
        const uint32_t B_hi = stA[s] + 32768u, B_lo = stA[s] + 49152u;

#pragma unroll
        for (int ks = 0; ks < 4; ks++) {
            const int kb = ks * 32;
            uint32_t ah[2][4], al[2][4], bh[4][2], bl[4][2];
            {
                const int g = lane >> 3;
                const int arow = (lane & 7) + ((g & 1) << 3);
                const int akc  = kb + ((g >> 1) << 4);
#pragma unroll
                for (int tn = 0; tn < 2; tn++) {
                    uint32_t off = SW128(((warp_i + tn * 16 + arow) << 7) + akc);
                    ldsm4(ah[tn], A_hi + off);
                    ldsm4(al[tn], A_lo + off);
                }
                const int brow = (lane & 7) + ((g >> 1) << 3);
                const int bkc  = kb + ((g & 1) << 4);
#pragma unroll
                for (int p = 0; p < 2; p++) {
                    uint32_t off = SW128(((warp_j + p * 16 + brow) << 7) + bkc);
                    uint32_t r4[4];
                    ldsm4(r4, B_hi + off);
                    bh[p * 2][0] = r4[0]; bh[p * 2][1] = r4[1];
                    bh[p * 2 + 1][0] = r4[2]; bh[p * 2 + 1][1] = r4[3];
                    ldsm4(r4, B_lo + off);
                    bl[p * 2][0] = r4[0]; bl[p * 2][1] = r4[1];
                    bl[p * 2 + 1][0] = r4[2]; bl[p * 2 + 1][1] = r4[3];
                }
            }
#pragma unroll
            for (int tn = 0; tn < 2; tn++)
#pragma unroll
                for (int tm = 0; tm < 4; tm++) {
                    mma_bf16(acc[tn][tm], ah[tn], bh[tm]);
                    mma_bf16(acc[tn][tm], al[tn], bh[tm]);
                    mma_bf16(acc[tn][tm], ah[tn], bl[tm]);
                }
        }
        __syncthreads();
        if (c + 2 < nCh) { load_chunk(c + 2, s); CP_COMMIT(); }
    }

    const int li = lane >> 2;
    const int lj = (lane & 3) * 2;
#pragma unroll
    for (int tn = 0; tn < 2; tn++) {
#pragma unroll
        for (int tm = 0; tm < 4; tm++) {
            int i0 = warp_i + tn * 16 + li;
            int j0 = warp_j + tm * 8 + lj;
            if (MODE == 1) {
                float bj0 = bias[bRow0 + j0], bj1 = bias[bRow0 + j0 + 1];
#pragma unroll
                for (int h = 0; h < 2; h++) {
                    float v0 = fmaxf(acc[tn][tm][h * 2 + 0] + bj0, 0.f);
                    float v1 = fmaxf(acc[tn][tm][h * 2 + 1] + bj1, 0.f);
                    __nv_bfloat16 h0 = __float2bfloat16(v0);
                    __nv_bfloat16 h1 = __float2bfloat16(v1);
                    __nv_bfloat162 hv; hv.x = h0; hv.y = h1;
                    __nv_bfloat162 lv;
                    lv.x = __float2bfloat16(v0 - __bfloat162float(h0));
                    lv.y = __float2bfloat16(v1 - __bfloat162float(h1));
                    size_t o = (size_t)(aRow0 + i0 + h * 8) * ost + bRow0 + j0;
                    *(__nv_bfloat162*)&outHi[o] = hv;
                    *(__nv_bfloat162*)&outLo[o] = lv;
                }
            } else {
#pragma unroll
                for (int h = 0; h < 2; h++) {
                    int i = i0 + h * 8;
                    if (i < Mreal) {
                        float bi = bias[i];
                        float2 v = make_float2(acc[tn][tm][h * 2 + 0] + bi,
                                               acc[tn][tm][h * 2 + 1] + bi);
                        *(float2*)&outF[(size_t)i * ost + bRow0 + j0] = v;
                    }
                }
            }
        }
    }
}

// ===================== attention: HMMA QK + FFMA sqrt/exp softmax =====================
// Block: 32 q rows x 512 k, one batch. 512 threads (16 warps: 2(i) x 8(j)).
// smem layout identical to R13: Q 16KB @0, K stages 128KB @16384,
// Dsm [32][516] @147456, q2s @213504, k2s @213632, mask @215680.
#define ATT_SMEM 217728
#define DSTA 516

__global__ __launch_bounds__(512)
void attn_kernel(const __nv_bfloat16* __restrict__ qhi, const __nv_bfloat16* __restrict__ qlo,
                 const __nv_bfloat16* __restrict__ khi, const __nv_bfloat16* __restrict__ klo,
                 const float* __restrict__ q2g, const float* __restrict__ k2g,
                 const int* __restrict__ mask,
                 float* __restrict__ attn_out, float* __restrict__ logp_out)
{
    extern __shared__ __align__(1024) char smraw[];
    const uint32_t sbase = smem_u32(smraw);
    const uint32_t QHI = sbase, QLO = sbase + 8192u;
    const uint32_t KST = sbase + 16384u;
    float* Dsm   = (float*)(smraw + 147456);
    float* q2s   = (float*)(smraw + 213504);
    float* k2s   = (float*)(smraw + 213632);
    int*   maskS = (int*)  (smraw + 215680);

    const int b   = blockIdx.y;
    const int q0  = blockIdx.x * 32;
    const int tid = threadIdx.x;
    const int wid = tid >> 5, lane = tid & 31;
    const int nq0 = b * 2048 + q0;
    const int nk0 = b * 512;

    // ---- load Q tiles (cp.async): 1024 ops over 512 threads ----
#pragma unroll
    for (int it = 0; it < 2; it++) {
        int idx = tid + it * 512;            // 0..1023
        int half = idx >> 9;                 // 0 hi, 1 lo
        int rem  = idx & 511;
        int h    = rem >> 8;
        int rr   = (rem >> 3) & 31;
        int g    = rem & 7;
        const __nv_bfloat16* src = (half ? qlo : qhi);
        cpa16((half ? QLO : QHI) + h * 4096u + SW128((rr << 7) + (g << 4)),
              src + (size_t)(nq0 + rr) * 128 + h * 64 + g * 8);
    }
    auto load_k = [&](int kc, int s) {
        const uint32_t base = KST + (uint32_t)s * 65536u;
#pragma unroll
        for (int it = 0; it < 8; it++) {
            int idx = tid + it * 512;        // 0..4095
            int half = idx >> 11;
            int rem  = idx & 2047;
            int h    = rem >> 10;
            int rr   = (rem >> 3) & 127;
            int g    = rem & 7;
            const __nv_bfloat16* src = (half ? klo : khi);
            cpa16(base + half * 32768u + h * 16384u + SW128((rr << 7) + (g << 4)),
                  src + (size_t)(nk0 + kc * 128 + rr) * 128 + h * 64 + g * 8);
        }
    };
    load_k(0, 0); CP_COMMIT();
    load_k(1, 1); CP_COMMIT();

    if (tid < 32)  q2s[tid] = q2g[nq0 + tid];
    if (tid >= 512 - 512 && tid < 512) {
        int i = tid;
        if (i < 512) { k2s[i] = k2g[nk0 + i]; maskS[i] = mask[nk0 + i]; }
    }

    const int li = lane >> 2;
    const int lj = (lane & 3) * 2;
    const int warp_i = (wid >> 3) * 16;      // 0 or 16
    const int wj = (wid & 7) * 16;           // 0..112

    for (int kc = 0; kc < 4; kc++) {
        const int s = kc & 1;
        if (kc + 1 < 4) asm volatile("cp.async.wait_group 1;" ::: "memory");
        else            asm volatile("cp.async.wait_group 0;" ::: "memory");
        __syncthreads();

        float acc[2][4];
#pragma unroll
        for (int c2 = 0; c2 < 2; c2++)
#pragma unroll
            for (int r = 0; r < 4; r++) acc[c2][r] = 0.f;

        const uint32_t KB = KST + (uint32_t)s * 65536u;
#pragma unroll
        for (int ks = 0; ks < 8; ks++) {
            const int h  = ks >> 2;
            const int kb = (ks & 3) * 32;
            const int g  = lane >> 3;
            uint32_t ah[4], al[4], bh[2][2], bl[2][2];
            {
                const int arow = (lane & 7) + ((g & 1) << 3);
                const int akc  = kb + ((g >> 1) << 4);
                uint32_t offA = (uint32_t)h * 4096u + SW128(((warp_i + arow) << 7) + akc);
                ldsm4(ah, QHI + offA);
                ldsm4(al, QLO + offA);
                const int brow = (lane & 7) + ((g >> 1) << 3);
                const int bkc  = kb + ((g & 1) << 4);
                uint32_t off = (uint32_t)h * 16384u + SW128(((wj + brow) << 7) + bkc);
                uint32_t r4[4];
                ldsm4(r4, KB + off);
                bh[0][0] = r4[0]; bh[0][1] = r4[1]; bh[1][0] = r4[2]; bh[1][1] = r4[3];
                ldsm4(r4, KB + 32768u + off);
                bl[0][0] = r4[0]; bl[0][1] = r4[1]; bl[1][0] = r4[2]; bl[1][1] = r4[3];
            }
#pragma unroll
            for (int tm = 0; tm < 2; tm++) {
                mma_bf16(acc[tm], ah, bh[tm]);
                mma_bf16(acc[tm], al, bh[tm]);
                mma_bf16(acc[tm], ah, bl[tm]);
            }
        }

        // epilogue: d = sqrt(max(q2+k2-2qk,1e-12)), mask, -> Dsm
#pragma unroll
        for (int tm = 0; tm < 2; tm++)
#pragma unroll
            for (int hh = 0; hh < 2; hh++) {
                int i  = warp_i + hh * 8 + li;
                int kg = kc * 128 + wj + tm * 8 + lj;
                float q2v = q2s[i];
                float d0 = q2v + k2s[kg]     - 2.f * acc[tm][hh * 2 + 0];
                float d1 = q2v + k2s[kg + 1] - 2.f * acc[tm][hh * 2 + 1];
                d0 = sqrt_fast(fmaxf(d0, 1e-12f));
                d1 = sqrt_fast(fmaxf(d1, 1e-12f));
                if (maskS[kg]     == 0) d0 = -FLT_MAX;
                if (maskS[kg + 1] == 0) d1 = -FLT_MAX;
                *(float2*)&Dsm[i * DSTA + kg] = make_float2(d0, d1);
            }
        __syncthreads();
        if (kc + 2 < 4) { load_k(kc + 2, s); CP_COMMIT(); }
    }

    // ---- logp write (coalesced float4): 4096 over 512 threads ----
    const size_t rowbase = ((size_t)b * 2048 + q0) * 512;
#pragma unroll
    for (int it = 0; it < 8; it++) {
        int idx = tid + it * 512;
        int qi = idx >> 7;
        int c4 = (idx & 127) * 4;
        float4 v = *(const float4*)&Dsm[qi * DSTA + c4];
        *(float4*)&logp_out[rowbase + (size_t)qi * 512 + c4] = v;
    }

    // ---- softmax: warp w handles rows w*2, w*2+1 ----
#pragma unroll
    for (int r = 0; r < 2; r++) {
        int qi = wid * 2 + r;
        float vals[16];
        float mx = -FLT_MAX;
#pragma unroll
        for (int j = 0; j < 16; j++) {
            vals[j] = Dsm[qi * DSTA + lane + j * 32];
            mx = fmaxf(mx, vals[j]);
        }
#pragma unroll
        for (int off = 16; off; off >>= 1)
            mx = fmaxf(mx, __shfl_xor_sync(0xffffffffu, mx, off));
        float s = 0.f;
#pragma unroll
        for (int j = 0; j < 16; j++) { vals[j] = exp_fast(vals[j] - mx); s += vals[j]; }
#pragma unroll
        for (int off = 16; off; off >>= 1)
            s += __shfl_xor_sync(0xffffffffu, s, off);
        float inv = 1.f / s;
#pragma unroll
        for (int j = 0; j < 16; j++)
            attn_out[rowbase + (size_t)qi * 512 + lane + j * 32] = vals[j] * inv;
    }
}

// ---------------------------------------------------------------------------
extern "C" void kernel_launch(void* const* d_in, const int* in_sizes, int n_in,
                              void* d_out, int out_size)
{
    const float* queries = (const float*)d_in[0];
    const float* keys    = (const float*)d_in[1];
    const int*   mask    = (const int*)d_in[2];
    const float* kw1 = (const float*)d_in[3];
    const float* kb1 = (const float*)d_in[4];
    const float* kw2 = (const float*)d_in[5];
    const float* kb2 = (const float*)d_in[6];
    const float* qw1 = (const float*)d_in[7];
    const float* qb1 = (const float*)d_in[8];
    const float* qw2 = (const float*)d_in[9];
    const float* qb2 = (const float*)d_in[10];
    const float* qw3 = (const float*)d_in[11];
    const float* qb3 = (const float*)d_in[12];

    __nv_bfloat16 *bthi, *btlo, *w1hi, *w1lo, *hthi, *htlo, *w2hi, *w2lo;
    __nv_bfloat16 *btqhi, *btqlo, *qw1hi, *qw1lo, *q1hi, *q1lo;
    __nv_bfloat16 *qw2hi, *qw2lo, *q2hi, *q2lo, *qw3hi, *qw3lo;
    __nv_bfloat16 *qfthi, *qftlo, *kfthi, *kftlo;
    float *kf, *qf, *qb1p, *qb2p, *qb3p, *kb2p, *q2n, *k2n;
    cudaGetSymbolAddress((void**)&bthi, g_Bthi);
    cudaGetSymbolAddress((void**)&btlo, g_Btlo);
    cudaGetSymbolAddress((void**)&w1hi, g_w1hi);
    cudaGetSymbolAddress((void**)&w1lo, g_w1lo);
    cudaGetSymbolAddress((void**)&hthi, g_hThi);
    cudaGetSymbolAddress((void**)&htlo, g_hTlo);
    cudaGetSymbolAddress((void**)&w2hi, g_w2hi);
    cudaGetSymbolAddress((void**)&w2lo, g_w2lo);
    cudaGetSymbolAddress((void**)&btqhi, g_BtQhi);
    cudaGetSymbolAddress((void**)&btqlo, g_BtQlo);
    cudaGetSymbolAddress((void**)&qw1hi, g_qw1hi);
    cudaGetSymbolAddress((void**)&qw1lo, g_qw1lo);
    cudaGetSymbolAddress((void**)&q1hi, g_q1hi);
    cudaGetSymbolAddress((void**)&q1lo, g_q1lo);
    cudaGetSymbolAddress((void**)&qw2hi, g_qw2hi);
    cudaGetSymbolAddress((void**)&qw2lo, g_qw2lo);
    cudaGetSymbolAddress((void**)&q2hi, g_q2hi);
    cudaGetSymbolAddress((void**)&q2lo, g_q2lo);
    cudaGetSymbolAddress((void**)&qw3hi, g_qw3hi);
    cudaGetSymbolAddress((void**)&qw3lo, g_qw3lo);
    cudaGetSymbolAddress((void**)&qfthi, g_qfThi);
    cudaGetSymbolAddress((void**)&qftlo, g_qfTlo);
    cudaGetSymbolAddress((void**)&kfthi, g_kfThi);
    cudaGetSymbolAddress((void**)&kftlo, g_kfTlo);
    cudaGetSymbolAddress((void**)&kf, g_kf);
    cudaGetSymbolAddress((void**)&qf, g_qf);
    cudaGetSymbolAddress((void**)&qb1p, g_qb1p);
    cudaGetSymbolAddress((void**)&qb2p, g_qb2p);
    cudaGetSymbolAddress((void**)&qb3p, g_qb3p);
    cudaGetSymbolAddress((void**)&kb2p, g_kb2p);
    cudaGetSymbolAddress((void**)&q2n, g_q2n);
    cudaGetSymbolAddress((void**)&k2n, g_k2n);

    cudaFuncSetAttribute(mmk<1>, cudaFuncAttributeMaxDynamicSharedMemorySize, MMK_SMEM);
    cudaFuncSetAttribute(mmk<2>, cudaFuncAttributeMaxDynamicSharedMemorySize, MMK_SMEM);
    cudaFuncSetAttribute(attn_kernel, cudaFuncAttributeMaxDynamicSharedMemorySize, ATT_SMEM);

    // ---- prep ----
    split_pad2<<<(1024 * 1536) / 256, 256>>>(kw1, w1hi, w1lo, 1024, 1536, 1536, 1024 * 1536);
    split_pad2<<<(128 * 1024) / 256, 256>>>(kw2, w2hi, w2lo, 80, 1024, 1024, 128 * 1024);
    split_pad2<<<(256 * 256) / 256, 256>>>(qw1, qw1hi, qw1lo, 160, 240, 256, 256 * 256);
    split_pad2<<<(128 * 256) / 256, 256>>>(qw2, qw2hi, qw2lo, 80, 160, 256, 128 * 256);
    split_pad2<<<(128 * 128) / 256, 256>>>(qw3, qw3hi, qw3lo, 80, 80, 128, 128 * 128);
    pad_bias<<<1, 256>>>(qb1, qb1p, 160, 256);
    pad_bias<<<1, 256>>>(qb2, qb2p, 80, 128);
    pad_bias<<<1, 256>>>(qb3, qb3p, 80, 128);
    pad_bias<<<1, 256>>>(kb2, kb2p, 80, 128);
    build_Bt<<<dim3(64, 8), 256>>>(keys, bthi, btlo);
    build_BtQ<<<256, 256>>>(queries, btqhi, btqlo);

    // ---- K path ----
    mmk<1><<<dim3(64, 8), 512, MMK_SMEM>>>(bthi, btlo, w1hi, w1lo, kb1,
                                           hthi, htlo, nullptr, 1536, 1024, 0);
    mmk<2><<<dim3(64, 1), 512, MMK_SMEM>>>(w2hi, w2lo, hthi, htlo, kb2p,
                                           nullptr, nullptr, kf, 1024, NK, 80);

    // ---- Q path ----
    mmk<1><<<dim3(256, 2), 512, MMK_SMEM>>>(btqhi, btqlo, qw1hi, qw1lo, qb1p,
                                            q1hi, q1lo, nullptr, 256, 256, 0);
    mmk<1><<<dim3(256, 1), 512, MMK_SMEM>>>(q1hi, q1lo, qw2hi, qw2lo, qb2p,
                                            q2hi, q2lo, nullptr, 256, 128, 0);
    mmk<2><<<dim3(256, 1), 512, MMK_SMEM>>>(qw3hi, qw3lo, q2hi, q2lo, qb3p,
                                            nullptr, nullptr, qf, 128, NQ, 80);

    // ---- transpose/split features + norms for attention ----
    cvtT<<<NQ / 128, 256>>>(qf, NQ, qfthi, qftlo, q2n);
    cvtT<<<NK / 128, 256>>>(kf, NK, kfthi, kftlo, k2n);

    // ---- attention + softmax ----
    float* attn = (float*)d_out;
    float* logp = attn + (size_t)16 * 2048 * 512;
    attn_kernel<<<dim3(2048 / 32, 16), 512, ATT_SMEM>>>(qfthi, qftlo, kfthi, kftlo,
                                                        q2n, k2n, mask, attn, logp);
}

// round 16
// speedup vs baseline: 2.8008x; 1.0372x over previous
#include <cuda_runtime.h>
#include <cuda_bf16.h>
#include <math.h>
#include <float.h>
#include <stdint.h>

#define NK 8192      // 16*512
#define NQ 32768     // 16*2048

// ---- K path buffers ----
__device__ __nv_bfloat16 g_Bthi[8192u * 1536];
__device__ __nv_bfloat16 g_Btlo[8192u * 1536];
__device__ __nv_bfloat16 g_w1hi[1024u * 1536];
__device__ __nv_bfloat16 g_w1lo[1024u * 1536];
__device__ __nv_bfloat16 g_hThi[8192u * 1024];
__device__ __nv_bfloat16 g_hTlo[8192u * 1024];
__device__ __nv_bfloat16 g_w2hi[128u * 1024];
__device__ __nv_bfloat16 g_w2lo[128u * 1024];
__device__ float g_kf[80u * NK];
// ---- Q path buffers ----
__device__ __nv_bfloat16 g_BtQhi[32768u * 256];
__device__ __nv_bfloat16 g_BtQlo[32768u * 256];
__device__ __nv_bfloat16 g_qw1hi[256u * 256];
__device__ __nv_bfloat16 g_qw1lo[256u * 256];
__device__ __nv_bfloat16 g_q1hi[32768u * 256];
__device__ __nv_bfloat16 g_q1lo[32768u * 256];
__device__ __nv_bfloat16 g_qw2hi[128u * 256];
__device__ __nv_bfloat16 g_qw2lo[128u * 256];
__device__ __nv_bfloat16 g_q2hi[32768u * 128];
__device__ __nv_bfloat16 g_q2lo[32768u * 128];
__device__ __nv_bfloat16 g_qw3hi[128u * 128];
__device__ __nv_bfloat16 g_qw3lo[128u * 128];
__device__ float g_qf[80u * NQ];
// ---- attn transposed features + norms ----
__device__ __nv_bfloat16 g_qfThi[32768u * 128];
__device__ __nv_bfloat16 g_qfTlo[32768u * 128];
__device__ __nv_bfloat16 g_kfThi[8192u * 128];
__device__ __nv_bfloat16 g_kfTlo[8192u * 128];
__device__ float g_q2n[32768];
__device__ float g_k2n[8192];
// ---- padded biases ----
__device__ float g_qb1p[256];
__device__ float g_qb2p[128];
__device__ float g_qb3p[128];
__device__ float g_kb2p[128];

// =========================== PTX helpers (sm_80+ baseline) ===========================
__device__ __forceinline__ uint32_t smem_u32(const void* p) {
    return (uint32_t)__cvta_generic_to_shared(p);
}
#define SW128(x) ((x) ^ (((x) >> 3) & 0x70))

__device__ __forceinline__ void cpa16(uint32_t dst, const void* src) {
    asm volatile("cp.async.cg.shared.global [%0], [%1], 16;\n" :: "r"(dst), "l"(src));
}
#define CP_COMMIT() asm volatile("cp.async.commit_group;\n" ::: "memory")

__device__ __forceinline__ void ldsm4(uint32_t* r, uint32_t addr) {
    asm volatile("ldmatrix.sync.aligned.m8n8.x4.shared.b16 {%0,%1,%2,%3}, [%4];"
                 : "=r"(r[0]), "=r"(r[1]), "=r"(r[2]), "=r"(r[3]) : "r"(addr));
}

__device__ __forceinline__ void mma_bf16(float* c, const uint32_t* a, const uint32_t* b) {
    asm volatile(
        "mma.sync.aligned.m16n8k16.row.col.f32.bf16.bf16.f32 "
        "{%0,%1,%2,%3}, {%4,%5,%6,%7}, {%8,%9}, {%0,%1,%2,%3};\n"
        : "+f"(c[0]), "+f"(c[1]), "+f"(c[2]), "+f"(c[3])
        : "r"(a[0]), "r"(a[1]), "r"(a[2]), "r"(a[3]), "r"(b[0]), "r"(b[1]));
}

// FFMA-only sqrt: magic rsqrt + 2 Newton iterations (rel err ~4e-6). No MUFU.
__device__ __forceinline__ float sqrt_fast(float x) {
    float y = __int_as_float(0x5f3759dfu - (__float_as_int(x) >> 1));
    y = y * fmaf(-0.5f * x * y, y, 1.5f);
    y = y * fmaf(-0.5f * x * y, y, 1.5f);
    return x * y;
}

// FFMA-only exp (exp2 range reduction + deg-5 poly). Valid for x <= 0.
__device__ __forceinline__ float exp_fast(float x) {
    float t = x * 1.4426950408889634f;
    t = fmaxf(t, -126.0f);
    float fn = t + 12582912.0f;
    float n  = fn - 12582912.0f;
    float f  = t - n;
    float p  = 1.3333558e-3f;
    p = fmaf(p, f, 9.6181291e-3f);
    p = fmaf(p, f, 5.5504109e-2f);
    p = fmaf(p, f, 2.4022651e-1f);
    p = fmaf(p, f, 6.9314718e-1f);
    p = fmaf(p, f, 1.0f);
    float sc = __int_as_float(((int)n + 127) << 23);
    return p * sc;
}

// =========================== prep kernels ===========================
__global__ void split_pad2(const float* __restrict__ in, __nv_bfloat16* __restrict__ hi,
                           __nv_bfloat16* __restrict__ lo, int R, int C, int outC, int total)
{
    int idx = blockIdx.x * 256 + threadIdx.x;
    if (idx >= total) return;
    int row = idx / outC, col = idx - row * outC;
    float v = (row < R && col < C) ? in[row * C + col] : 0.f;
    __nv_bfloat16 h = __float2bfloat16(v);
    hi[idx] = h;
    lo[idx] = __float2bfloat16(v - __bfloat162float(h));
}

__global__ void pad_bias(const float* __restrict__ in, float* __restrict__ out, int C, int outC)
{
    int i = threadIdx.x;
    if (i < outC) out[i] = (i < C) ? in[i] : 0.f;
}

__global__ __launch_bounds__(256)
void build_Bt(const float* __restrict__ keys,
              __nv_bfloat16* __restrict__ bhi, __nv_bfloat16* __restrict__ blo)
{
    __shared__ float sk[64][131];
    const int tid = threadIdx.x;
    const int nt = blockIdx.x;
    const int cc = blockIdx.y * 64;
    const int b  = nt >> 2;
    const int t0 = (nt & 3) * 128;
    const int n0 = b * 512 + t0;

    for (int idx = tid; idx < 64 * 130; idx += 256) {
        int cl = idx / 130, tt = idx - cl * 130;
        int ts = t0 + tt - 1;
        sk[cl][tt] = ((unsigned)ts < 512u)
                     ? keys[((size_t)b * 512 + cc + cl) * 512 + ts] : 0.f;
    }
    __syncthreads();
    for (int idx = tid; idx < 128 * 192; idx += 256) {
        int tl = idx / 192, r = idx - tl * 192;
        int cl = r / 3, dt = r - cl * 3;
        float v = sk[cl][tl + dt];
        __nv_bfloat16 h = __float2bfloat16(v);
        size_t o = (size_t)(n0 + tl) * 1536 + cc * 3 + r;
        bhi[o] = h;
        blo[o] = __float2bfloat16(v - __bfloat162float(h));
    }
}

__global__ __launch_bounds__(256)
void build_BtQ(const float* __restrict__ queries,
               __nv_bfloat16* __restrict__ bhi, __nv_bfloat16* __restrict__ blo)
{
    __shared__ float sk[80][131];
    const int tid = threadIdx.x;
    const int nt = blockIdx.x;
    const int b  = nt >> 4;
    const int t0 = (nt & 15) * 128;
    const int n0 = b * 2048 + t0;

    for (int idx = tid; idx < 80 * 130; idx += 256) {
        int cl = idx / 130, tt = idx - cl * 130;
        int ts = t0 + tt - 1;
        sk[cl][tt] = ((unsigned)ts < 2048u)
                     ? queries[((size_t)b * 80 + cl) * 2048 + ts] : 0.f;
    }
    __syncthreads();
    for (int idx = tid; idx < 128 * 256; idx += 256) {
        int tl = idx >> 8, r = idx & 255;
        float v = 0.f;
        if (r < 240) {
            int cl = r / 3, dt = r - cl * 3;
            v = sk[cl][tl + dt];
        }
        __nv_bfloat16 h = __float2bfloat16(v);
        size_t o = (size_t)(n0 + tl) * 256 + r;
        bhi[o] = h;
        blo[o] = __float2bfloat16(v - __bfloat162float(h));
    }
}

// Transpose [80][N] fp32 -> [n][128] bf16 hi/lo (c padded to 128) + fp32 norms.
__global__ __launch_bounds__(256)
void cvtT(const float* __restrict__ src, int N,
          __nv_bfloat16* __restrict__ dhi, __nv_bfloat16* __restrict__ dlo,
          float* __restrict__ nrm)
{
    __shared__ float s[80][132];
    const int tid = threadIdx.x;
    const int n0 = blockIdx.x * 128;
    for (int q = tid; q < 80 * 32; q += 256) {
        int c = q >> 5, j = (q & 31) * 4;
        *(float4*)&s[c][j] = *(const float4*)&src[(size_t)c * N + n0 + j];
    }
    __syncthreads();
    for (int idx = tid; idx < 128 * 128; idx += 256) {
        int nl = idx >> 7, c = idx & 127;
        float v = (c < 80) ? s[c][nl] : 0.f;
        __nv_bfloat16 h = __float2bfloat16(v);
        size_t o = (size_t)(n0 + nl) * 128 + c;
        dhi[o] = h;
        dlo[o] = __float2bfloat16(v - __bfloat162float(h));
    }
    if (tid < 128) {
        float sum = 0.f;
        for (int c = 0; c < 80; c++) { float v = s[c][tid]; sum += v * v; }
        nrm[n0 + tid] = sum;
    }
}

// ===================== mma.sync bf16x3 GEMM (unchanged) =====================
#define MMK_SMEM 131072

template<int MODE>
__global__ __launch_bounds__(512)
void mmk(const __nv_bfloat16* __restrict__ aHi, const __nv_bfloat16* __restrict__ aLo,
         const __nv_bfloat16* __restrict__ bHi, const __nv_bfloat16* __restrict__ bLo,
         const float* __restrict__ bias,
         __nv_bfloat16* __restrict__ outHi, __nv_bfloat16* __restrict__ outLo,
         float* __restrict__ outF, int Kdim, int ost, int Mreal)
{
    extern __shared__ __align__(1024) char smx[];
    const int tid  = threadIdx.x;
    const int wid  = tid >> 5, lane = tid & 31;
    const int nCh  = Kdim >> 6;

    const int aRow0 = (MODE == 1) ? blockIdx.x * 128 : 0;
    const int bRow0 = (MODE == 1) ? blockIdx.y * 128 : blockIdx.x * 128;

    const int warp_i = (wid >> 2) * 32;
    const int warp_j = (wid & 3) * 32;

    const uint32_t sbase = smem_u32(smx);
    const uint32_t stA[2] = { sbase, sbase + 65536u };

    auto load_chunk = [&](int c, int s) {
        const uint32_t base = stA[s];
        const size_t cb = (size_t)c * 64;
#pragma unroll
        for (int it = 0; it < 8; it++) {
            int idx = tid + it * 512;
            int mat = idx >> 10;
            int r   = (idx & 1023) >> 3;
            int g   = idx & 7;
            const __nv_bfloat16* srcm =
                (mat == 0) ? aHi : (mat == 1) ? aLo : (mat == 2) ? bHi : bLo;
            int row0 = (mat < 2) ? aRow0 : bRow0;
            cpa16(base + mat * 16384u + SW128((r << 7) + (g << 4)),
                  srcm + (size_t)(row0 + r) * Kdim + cb + g * 8);
        }
    };

    load_chunk(0, 0); CP_COMMIT();
    load_chunk(1, 1); CP_COMMIT();

    float acc[2][4][4];
#pragma unroll
    for (int a = 0; a < 2; a++)
#pragma unroll
        for (int b = 0; b < 4; b++)
#pragma unroll
            for (int r = 0; r < 4; r++) acc[a][b][r] = 0.f;

    for (int c = 0; c < nCh; c++) {
        const int s = c & 1;
        if (c + 1 < nCh) asm volatile("cp.async.wait_group 1;" ::: "memory");
        else             asm volatile("cp.async.wait_group 0;" ::: "memory");
        __syncthreads();

        const uint32_t A_hi = stA[s], A_lo = stA[s] + 16384u;
        const uint32_t B_hi = stA[s] + 32768u, B_lo = stA[s] + 49152u;

#pragma unroll
        for (int ks = 0; ks < 4; ks++) {
            const int kb = ks * 32;
            uint32_t ah[2][4], al[2][4], bh[4][2], bl[4][2];
            {
                const int g = lane >> 3;
                const int arow = (lane & 7) + ((g & 1) << 3);
                const int akc  = kb + ((g >> 1) << 4);
#pragma unroll
                for (int tn = 0; tn < 2; tn++) {
                    uint32_t off = SW128(((warp_i + tn * 16 + arow) << 7) + akc);
                    ldsm4(ah[tn], A_hi + off);
                    ldsm4(al[tn], A_lo + off);
                }
                const int brow = (lane & 7) + ((g >> 1) << 3);
                const int bkc  = kb + ((g & 1) << 4);
#pragma unroll
                for (int p = 0; p < 2; p++) {
                    uint32_t off = SW128(((warp_j + p * 16 + brow) << 7) + bkc);
                    uint32_t r4[4];
                    ldsm4(r4, B_hi + off);
                    bh[p * 2][0] = r4[0]; bh[p * 2][1] = r4[1];
                    bh[p * 2 + 1][0] = r4[2]; bh[p * 2 + 1][1] = r4[3];
                    ldsm4(r4, B_lo + off);
                    bl[p * 2][0] = r4[0]; bl[p * 2][1] = r4[1];
                    bl[p * 2 + 1][0] = r4[2]; bl[p * 2 + 1][1] = r4[3];
                }
            }
#pragma unroll
            for (int tn = 0; tn < 2; tn++)
#pragma unroll
                for (int tm = 0; tm < 4; tm++) {
                    mma_bf16(acc[tn][tm], ah[tn], bh[tm]);
                    mma_bf16(acc[tn][tm], al[tn], bh[tm]);
                    mma_bf16(acc[tn][tm], ah[tn], bl[tm]);
                }
        }
        __syncthreads();
        if (c + 2 < nCh) { load_chunk(c + 2, s); CP_COMMIT(); }
    }

    const int li = lane >> 2;
    const int lj = (lane & 3) * 2;
#pragma unroll
    for (int tn = 0; tn < 2; tn++) {
#pragma unroll
        for (int tm = 0; tm < 4; tm++) {
            int i0 = warp_i + tn * 16 + li;
            int j0 = warp_j + tm * 8 + lj;
            if (MODE == 1) {
                float bj0 = bias[bRow0 + j0], bj1 = bias[bRow0 + j0 + 1];
#pragma unroll
                for (int h = 0; h < 2; h++) {
                    float v0 = fmaxf(acc[tn][tm][h * 2 + 0] + bj0, 0.f);
                    float v1 = fmaxf(acc[tn][tm][h * 2 + 1] + bj1, 0.f);
                    __nv_bfloat16 h0 = __float2bfloat16(v0);
                    __nv_bfloat16 h1 = __float2bfloat16(v1);
                    __nv_bfloat162 hv; hv.x = h0; hv.y = h1;
                    __nv_bfloat162 lv;
                    lv.x = __float2bfloat16(v0 - __bfloat162float(h0));
                    lv.y = __float2bfloat16(v1 - __bfloat162float(h1));
                    size_t o = (size_t)(aRow0 + i0 + h * 8) * ost + bRow0 + j0;
                    *(__nv_bfloat162*)&outHi[o] = hv;
                    *(__nv_bfloat162*)&outLo[o] = lv;
                }
            } else {
#pragma unroll
                for (int h = 0; h < 2; h++) {
                    int i = i0 + h * 8;
                    if (i < Mreal) {
                        float bi = bias[i];
                        float2 v = make_float2(acc[tn][tm][h * 2 + 0] + bi,
                                               acc[tn][tm][h * 2 + 1] + bi);
                        *(float2*)&outF[(size_t)i * ost + bRow0 + j0] = v;
                    }
                }
            }
        }
    }
}

// ===================== attention: 128q x 512k per block, direct-GMEM logits =====================
// 512 threads (16 warps: 4(i) x 4(j)), warp tile 32q x 32k per chunk.
// smem: QHI @0 (32KB, two 16KB col-half tiles), QLO @32768,
//       K stages @65536: 2 x 64KB (KHI 32KB + KLO 32KB, each two 16KB h-tiles),
//       q2s @196608 (512B), k2s @197120 (2KB), maskS @199168 (2KB). Total 201216.
// Logits written straight to gmem as float2 (8 full 32B sectors per STG — coalesced).
// Softmax re-reads own logp rows (L2-hot) after threadfence_block.
#define ATT_SMEM 201216

__global__ __launch_bounds__(512)
void attn_kernel(const __nv_bfloat16* __restrict__ qhi, const __nv_bfloat16* __restrict__ qlo,
                 const __nv_bfloat16* __restrict__ khi, const __nv_bfloat16* __restrict__ klo,
                 const float* __restrict__ q2g, const float* __restrict__ k2g,
                 const int* __restrict__ mask,
                 float* __restrict__ attn_out, float* __restrict__ logp_out)
{
    extern __shared__ __align__(1024) char smraw[];
    const uint32_t sbase = smem_u32(smraw);
    const uint32_t QHI = sbase, QLO = sbase + 32768u;
    const uint32_t KST = sbase + 65536u;       // + s*65536; lo at +32768
    float* q2s   = (float*)(smraw + 196608);
    float* k2s   = (float*)(smraw + 197120);
    int*   maskS = (int*)  (smraw + 199168);

    const int b   = blockIdx.y;
    const int q0  = blockIdx.x * 128;
    const int tid = threadIdx.x;
    const int wid = tid >> 5, lane = tid & 31;
    const int nq0 = b * 2048 + q0;
    const int nk0 = b * 512;

    // ---- load Q tiles: 4096 cp.async over 512 threads ----
#pragma unroll
    for (int it = 0; it < 8; it++) {
        int idx = tid + it * 512;            // 0..4095
        int half = idx >> 11;                // 0 hi, 1 lo
        int rem  = idx & 2047;
        int h    = rem >> 10;                // col half
        int rr   = (rem >> 3) & 127;
        int g    = rem & 7;
        const __nv_bfloat16* src = (half ? qlo : qhi);
        cpa16((half ? QLO : QHI) + h * 16384u + SW128((rr << 7) + (g << 4)),
              src + (size_t)(nq0 + rr) * 128 + h * 64 + g * 8);
    }
    auto load_k = [&](int kc, int s) {
        const uint32_t base = KST + (uint32_t)s * 65536u;
#pragma unroll
        for (int it = 0; it < 8; it++) {
            int idx = tid + it * 512;        // 0..4095
            int half = idx >> 11;
            int rem  = idx & 2047;
            int h    = rem >> 10;
            int rr   = (rem >> 3) & 127;
            int g    = rem & 7;
            const __nv_bfloat16* src = (half ? klo : khi);
            cpa16(base + half * 32768u + h * 16384u + SW128((rr << 7) + (g << 4)),
                  src + (size_t)(nk0 + kc * 128 + rr) * 128 + h * 64 + g * 8);
        }
    };
    load_k(0, 0); CP_COMMIT();
    load_k(1, 1); CP_COMMIT();

    if (tid < 128) q2s[tid] = q2g[nq0 + tid];
    k2s[tid]   = k2g[nk0 + tid];
    maskS[tid] = mask[nk0 + tid];

    const int li = lane >> 2;
    const int lj = (lane & 3) * 2;
    const int warp_i = (wid >> 2) * 32;      // 0,32,64,96
    const int wj     = (wid & 3) * 32;       // 0,32,64,96

    const size_t rowbase = ((size_t)b * 2048 + q0) * 512;

    for (int kc = 0; kc < 4; kc++) {
        const int s = kc & 1;
        if (kc + 1 < 4) asm volatile("cp.async.wait_group 1;" ::: "memory");
        else            asm volatile("cp.async.wait_group 0;" ::: "memory");
        __syncthreads();

        float acc[2][4][4];
#pragma unroll
        for (int a = 0; a < 2; a++)
#pragma unroll
            for (int c2 = 0; c2 < 4; c2++)
#pragma unroll
                for (int r = 0; r < 4; r++) acc[a][c2][r] = 0.f;

        const uint32_t KB = KST + (uint32_t)s * 65536u;
#pragma unroll
        for (int ks = 0; ks < 8; ks++) {
            const int h  = ks >> 2;
            const int kb = (ks & 3) * 32;
            const int g  = lane >> 3;
            uint32_t ah[2][4], al[2][4], bh[4][2], bl[4][2];
            {
                const int arow = (lane & 7) + ((g & 1) << 3);
                const int akc  = kb + ((g >> 1) << 4);
#pragma unroll
                for (int tn = 0; tn < 2; tn++) {
                    uint32_t offA = (uint32_t)h * 16384u
                                  + SW128(((warp_i + tn * 16 + arow) << 7) + akc);
                    ldsm4(ah[tn], QHI + offA);
                    ldsm4(al[tn], QLO + offA);
                }
                const int brow = (lane & 7) + ((g >> 1) << 3);
                const int bkc  = kb + ((g & 1) << 4);
#pragma unroll
                for (int p = 0; p < 2; p++) {
                    uint32_t off = (uint32_t)h * 16384u
                                 + SW128(((wj + p * 16 + brow) << 7) + bkc);
                    uint32_t r4[4];
                    ldsm4(r4, KB + off);
                    bh[p * 2][0] = r4[0]; bh[p * 2][1] = r4[1];
                    bh[p * 2 + 1][0] = r4[2]; bh[p * 2 + 1][1] = r4[3];
                    ldsm4(r4, KB + 32768u + off);
                    bl[p * 2][0] = r4[0]; bl[p * 2][1] = r4[1];
                    bl[p * 2 + 1][0] = r4[2]; bl[p * 2 + 1][1] = r4[3];
                }
            }
#pragma unroll
            for (int tn = 0; tn < 2; tn++)
#pragma unroll
                for (int tm = 0; tm < 4; tm++) {
                    mma_bf16(acc[tn][tm], ah[tn], bh[tm]);
                    mma_bf16(acc[tn][tm], al[tn], bh[tm]);
                    mma_bf16(acc[tn][tm], ah[tn], bl[tm]);
                }
        }
        __syncthreads();                          // all ldsm of stage s done
        if (kc + 2 < 4) { load_k(kc + 2, s); CP_COMMIT(); }

        // epilogue: d = sqrt(max(q2+k2-2qk,1e-12)), mask, write logp (float2, full sectors)
#pragma unroll
        for (int tn = 0; tn < 2; tn++)
#pragma unroll
            for (int tm = 0; tm < 4; tm++)
#pragma unroll
                for (int hh = 0; hh < 2; hh++) {
                    int i  = warp_i + tn * 16 + hh * 8 + li;
                    int kg = kc * 128 + wj + tm * 8 + lj;
                    float q2v = q2s[i];
                    float d0 = q2v + k2s[kg]     - 2.f * acc[tn][tm][hh * 2 + 0];
                    float d1 = q2v + k2s[kg + 1] - 2.f * acc[tn][tm][hh * 2 + 1];
                    d0 = sqrt_fast(fmaxf(d0, 1e-12f));
                    d1 = sqrt_fast(fmaxf(d1, 1e-12f));
                    if (maskS[kg]     == 0) d0 = -FLT_MAX;
                    if (maskS[kg + 1] == 0) d1 = -FLT_MAX;
                    *(float2*)&logp_out[rowbase + (size_t)i * 512 + kg] = make_float2(d0, d1);
                }
    }

    __threadfence_block();
    __syncthreads();

    // ---- softmax: warp w handles rows w*8 .. w*8+7, re-reading own logp (L2-hot) ----
#pragma unroll
    for (int r = 0; r < 8; r++) {
        int qi = wid * 8 + r;
        const float* rowp = logp_out + rowbase + (size_t)qi * 512;
        float vals[16];
#pragma unroll
        for (int j = 0; j < 4; j++)
            *(float4*)&vals[j * 4] = *(const float4*)&rowp[lane * 4 + j * 128];
        float mx = -FLT_MAX;
#pragma unroll
        for (int j = 0; j < 16; j++) mx = fmaxf(mx, vals[j]);
#pragma unroll
        for (int off = 16; off; off >>= 1)
            mx = fmaxf(mx, __shfl_xor_sync(0xffffffffu, mx, off));
        float s = 0.f;
#pragma unroll
        for (int j = 0; j < 16; j++) { vals[j] = exp_fast(vals[j] - mx); s += vals[j]; }
#pragma unroll
        for (int off = 16; off; off >>= 1)
            s += __shfl_xor_sync(0xffffffffu, s, off);
        float inv = 1.f / s;
        float* rowo = attn_out + rowbase + (size_t)qi * 512;
#pragma unroll
        for (int j = 0; j < 4; j++) {
            float4 o;
            o.x = vals[j * 4 + 0] * inv; o.y = vals[j * 4 + 1] * inv;
            o.z = vals[j * 4 + 2] * inv; o.w = vals[j * 4 + 3] * inv;
            *(float4*)&rowo[lane * 4 + j * 128] = o;
        }
    }
}

// ---------------------------------------------------------------------------
extern "C" void kernel_launch(void* const* d_in, const int* in_sizes, int n_in,
                              void* d_out, int out_size)
{
    const float* queries = (const float*)d_in[0];
    const float* keys    = (const float*)d_in[1];
    const int*   mask    = (const int*)d_in[2];
    const float* kw1 = (const float*)d_in[3];
    const float* kb1 = (const float*)d_in[4];
    const float* kw2 = (const float*)d_in[5];
    const float* kb2 = (const float*)d_in[6];
    const float* qw1 = (const float*)d_in[7];
    const float* qb1 = (const float*)d_in[8];
    const float* qw2 = (const float*)d_in[9];
    const float* qb2 = (const float*)d_in[10];
    const float* qw3 = (const float*)d_in[11];
    const float* qb3 = (const float*)d_in[12];

    __nv_bfloat16 *bthi, *btlo, *w1hi, *w1lo, *hthi, *htlo, *w2hi, *w2lo;
    __nv_bfloat16 *btqhi, *btqlo, *qw1hi, *qw1lo, *q1hi, *q1lo;
    __nv_bfloat16 *qw2hi, *qw2lo, *q2hi, *q2lo, *qw3hi, *qw3lo;
    __nv_bfloat16 *qfthi, *qftlo, *kfthi, *kftlo;
    float *kf, *qf, *qb1p, *qb2p, *qb3p, *kb2p, *q2n, *k2n;
    cudaGetSymbolAddress((void**)&bthi, g_Bthi);
    cudaGetSymbolAddress((void**)&btlo, g_Btlo);
    cudaGetSymbolAddress((void**)&w1hi, g_w1hi);
    cudaGetSymbolAddress((void**)&w1lo, g_w1lo);
    cudaGetSymbolAddress((void**)&hthi, g_hThi);
    cudaGetSymbolAddress((void**)&htlo, g_hTlo);
    cudaGetSymbolAddress((void**)&w2hi, g_w2hi);
    cudaGetSymbolAddress((void**)&w2lo, g_w2lo);
    cudaGetSymbolAddress((void**)&btqhi, g_BtQhi);
    cudaGetSymbolAddress((void**)&btqlo, g_BtQlo);
    cudaGetSymbolAddress((void**)&qw1hi, g_qw1hi);
    cudaGetSymbolAddress((void**)&qw1lo, g_qw1lo);
    cudaGetSymbolAddress((void**)&q1hi, g_q1hi);
    cudaGetSymbolAddress((void**)&q1lo, g_q1lo);
    cudaGetSymbolAddress((void**)&qw2hi, g_qw2hi);
    cudaGetSymbolAddress((void**)&qw2lo, g_qw2lo);
    cudaGetSymbolAddress((void**)&q2hi, g_q2hi);
    cudaGetSymbolAddress((void**)&q2lo, g_q2lo);
    cudaGetSymbolAddress((void**)&qw3hi, g_qw3hi);
    cudaGetSymbolAddress((void**)&qw3lo, g_qw3lo);
    cudaGetSymbolAddress((void**)&qfthi, g_qfThi);
    cudaGetSymbolAddress((void**)&qftlo, g_qfTlo);
    cudaGetSymbolAddress((void**)&kfthi, g_kfThi);
    cudaGetSymbolAddress((void**)&kftlo, g_kfTlo);
    cudaGetSymbolAddress((void**)&kf, g_kf);
    cudaGetSymbolAddress((void**)&qf, g_qf);
    cudaGetSymbolAddress((void**)&qb1p, g_qb1p);
    cudaGetSymbolAddress((void**)&qb2p, g_qb2p);
    cudaGetSymbolAddress((void**)&qb3p, g_qb3p);
    cudaGetSymbolAddress((void**)&kb2p, g_kb2p);
    cudaGetSymbolAddress((void**)&q2n, g_q2n);
    cudaGetSymbolAddress((void**)&k2n, g_k2n);

    cudaFuncSetAttribute(mmk<1>, cudaFuncAttributeMaxDynamicSharedMemorySize, MMK_SMEM);
    cudaFuncSetAttribute(mmk<2>, cudaFuncAttributeMaxDynamicSharedMemorySize, MMK_SMEM);
    cudaFuncSetAttribute(attn_kernel, cudaFuncAttributeMaxDynamicSharedMemorySize, ATT_SMEM);

    // ---- prep ----
    split_pad2<<<(1024 * 1536) / 256, 256>>>(kw1, w1hi, w1lo, 1024, 1536, 1536, 1024 * 1536);
    split_pad2<<<(128 * 1024) / 256, 256>>>(kw2, w2hi, w2lo, 80, 1024, 1024, 128 * 1024);
    split_pad2<<<(256 * 256) / 256, 256>>>(qw1, qw1hi, qw1lo, 160, 240, 256, 256 * 256);
    split_pad2<<<(128 * 256) / 256, 256>>>(qw2, qw2hi, qw2lo, 80, 160, 256, 128 * 256);
    split_pad2<<<(128 * 128) / 256, 256>>>(qw3, qw3hi, qw3lo, 80, 80, 128, 128 * 128);
    pad_bias<<<1, 256>>>(qb1, qb1p, 160, 256);
    pad_bias<<<1, 256>>>(qb2, qb2p, 80, 128);
    pad_bias<<<1, 256>>>(qb3, qb3p, 80, 128);
    pad_bias<<<1, 256>>>(kb2, kb2p, 80, 128);
    build_Bt<<<dim3(64, 8), 256>>>(keys, bthi, btlo);
    build_BtQ<<<256, 256>>>(queries, btqhi, btqlo);

    // ---- K path ----
    mmk<1><<<dim3(64, 8), 512, MMK_SMEM>>>(bthi, btlo, w1hi, w1lo, kb1,
                                           hthi, htlo, nullptr, 1536, 1024, 0);
    mmk<2><<<dim3(64, 1), 512, MMK_SMEM>>>(w2hi, w2lo, hthi, htlo, kb2p,
                                           nullptr, nullptr, kf, 1024, NK, 80);

    // ---- Q path ----
    mmk<1><<<dim3(256, 2), 512, MMK_SMEM>>>(btqhi, btqlo, qw1hi, qw1lo, qb1p,
                                            q1hi, q1lo, nullptr, 256, 256, 0);
    mmk<1><<<dim3(256, 1), 512, MMK_SMEM>>>(q1hi, q1lo, qw2hi, qw2lo, qb2p,
                                            q2hi, q2lo, nullptr, 256, 128, 0);
    mmk<2><<<dim3(256, 1), 512, MMK_SMEM>>>(qw3hi, qw3lo, q2hi, q2lo, qb3p,
                                            nullptr, nullptr, qf, 128, NQ, 80);

    // ---- transpose/split features + norms for attention ----
    cvtT<<<NQ / 128, 256>>>(qf, NQ, qfthi, qftlo, q2n);
    cvtT<<<NK / 128, 256>>>(kf, NK, kfthi, kftlo, k2n);

    // ---- attention + softmax (128 q-rows per block) ----
    float* attn = (float*)d_out;
    float* logp = attn + (size_t)16 * 2048 * 512;
    attn_kernel<<<dim3(16, 16), 512, ATT_SMEM>>>(qfthi, qftlo, kfthi, kftlo,
                                                 q2n, k2n, mask, attn, logp);
}